// round 1
// baseline (speedup 1.0000x reference)
#include <cuda_runtime.h>
#include <math.h>
#include <stdint.h>

// Problem constants
#define BB 2
#define SS 1024
#define DD 512
#define VV 32000
#define MM 2048          // BB*SS rows
#define G3 1536          // 3*DD
#define GRU_CTAS 128

// ---------------- scratch (device globals; no runtime allocation) ----------------
__device__ float d_xproj[MM * G3];           // [s*2+b][1536]
__device__ float d_gru[MM * DD];             // [b*1024+s][512]
__device__ float d_h[2][BB * DD];            // ping-pong hidden state
__device__ unsigned d_bar;                   // grid barrier counter
__device__ float d_Q[MM * DD];
__device__ float d_Kc[MM * DD];
__device__ float d_probs[BB * SS * SS];      // scores -> probs (in place)
__device__ float d_ctx[MM * DD];
__device__ float d_comb[MM * 2 * DD];
__device__ float d_gate[MM];
__device__ float d_logits[65536000];         // 2048*32000
__device__ float d_rowmax[MM];
__device__ float d_rowsum[MM];

// =====================================================================
// K1: x_emb gather + x_proj = x_emb @ W_ih^T + b_ih   (64x64x16 tiles)
// C rows m = s*2 + b
// =====================================================================
__global__ void k_xproj(const int* __restrict__ x,
                        const float* __restrict__ tok_emb,
                        const float* __restrict__ pos_emb,
                        const float* __restrict__ W_ih,
                        const float* __restrict__ b_ih)
{
    const int m0 = blockIdx.y * 64;
    const int n0 = blockIdx.x * 64;
    __shared__ float As[16][64];
    __shared__ float Bs[16][64];
    __shared__ int tokS[64];
    __shared__ int sS[64];

    const int t = threadIdx.x;
    if (t < 64) {
        int m = m0 + t;
        int b = m & 1, s = m >> 1;
        tokS[t] = x[b * SS + s];
        sS[t] = s;
    }
    __syncthreads();

    const int lrow = t >> 2;
    const int lk4  = (t & 3) * 4;
    const int ty = t >> 4, tx = t & 15;
    float acc[4][4];
#pragma unroll
    for (int i = 0; i < 4; i++)
#pragma unroll
        for (int j = 0; j < 4; j++) acc[i][j] = 0.f;

    for (int k0 = 0; k0 < DD; k0 += 16) {
        float4 te = *(const float4*)&tok_emb[(size_t)tokS[lrow] * DD + k0 + lk4];
        float4 pe = *(const float4*)&pos_emb[(size_t)sS[lrow] * DD + k0 + lk4];
        float4 bv = *(const float4*)&W_ih[(size_t)(n0 + lrow) * DD + k0 + lk4];
        As[lk4 + 0][lrow] = te.x + pe.x;
        As[lk4 + 1][lrow] = te.y + pe.y;
        As[lk4 + 2][lrow] = te.z + pe.z;
        As[lk4 + 3][lrow] = te.w + pe.w;
        Bs[lk4 + 0][lrow] = bv.x;
        Bs[lk4 + 1][lrow] = bv.y;
        Bs[lk4 + 2][lrow] = bv.z;
        Bs[lk4 + 3][lrow] = bv.w;
        __syncthreads();
#pragma unroll
        for (int kk = 0; kk < 16; kk++) {
            float4 av = *(float4*)&As[kk][ty * 4];
            float4 bv2 = *(float4*)&Bs[kk][tx * 4];
            float a[4] = {av.x, av.y, av.z, av.w};
            float b2[4] = {bv2.x, bv2.y, bv2.z, bv2.w};
#pragma unroll
            for (int i = 0; i < 4; i++)
#pragma unroll
                for (int j = 0; j < 4; j++) acc[i][j] += a[i] * b2[j];
        }
        __syncthreads();
    }
#pragma unroll
    for (int i = 0; i < 4; i++) {
        int m = m0 + ty * 4 + i;
#pragma unroll
        for (int j = 0; j < 4; j++) {
            int n = n0 + tx * 4 + j;
            d_xproj[(size_t)m * G3 + n] = acc[i][j] + b_ih[n];
        }
    }
}

// =====================================================================
// K2: init barrier + h0
// =====================================================================
__global__ void k_init()
{
    int t = threadIdx.x;
    for (int i = t; i < 2 * BB * DD; i += blockDim.x) ((float*)d_h)[i] = 0.f;
    if (t == 0) d_bar = 0u;
}

// =====================================================================
// K3: GRU recurrence. 128 persistent CTAs, each owns 4 hidden dims.
// W_hh slice cached in SMEM. Grid barrier = monotonic atomic counter.
// =====================================================================
__global__ void k_gru(const float* __restrict__ W_hh,
                      const float* __restrict__ b_hh)
{
    __shared__ float Wsm[4 * 3 * DD];   // [dl][gate][512] : 24KB
    __shared__ float h_sm[BB * DD];     // 4KB

    const int t = threadIdx.x;
    const int c = blockIdx.x;
    const int d_base = c * 4;

    // load W_hh slice (6144 floats) as float4
    for (int i = t; i < 1536; i += 256) {
        int fi = i * 4;
        int dl = fi / 1536;
        int rem = fi - dl * 1536;
        int g = rem / 512;
        int k = rem & 511;
        *(float4*)&Wsm[fi] =
            *(const float4*)&W_hh[(size_t)(g * DD + d_base + dl) * DD + k];
    }

    const int w = t >> 5, lane = t & 31;
    const int b = w & 1, dl = w >> 1;       // 8 warps: 4 dims x 2 batches
    const int d = d_base + dl;
    const float bh_r = b_hh[d];
    const float bh_z = b_hh[DD + d];
    const float bh_n = b_hh[2 * DD + d];
    const float* Wr = &Wsm[(dl * 3 + 0) * DD];
    const float* Wz = &Wsm[(dl * 3 + 1) * DD];
    const float* Wn = &Wsm[(dl * 3 + 2) * DD];
    __syncthreads();

    for (int s = 0; s < SS; ++s) {
        if (s > 0 && t == 0) {
            unsigned target = (unsigned)GRU_CTAS * (unsigned)s;
            while (*(volatile unsigned*)&d_bar < target) {}
        }
        __syncthreads();

        // load full h (1024 floats) bypassing L1
        float4 hv = __ldcv((const float4*)&d_h[s & 1][0] + t);
        *(float4*)&h_sm[t * 4] = hv;
        __syncthreads();

        float xr = 0.f, xz = 0.f, xn = 0.f;
        if (lane == 0) {
            const float* xp = &d_xproj[(size_t)(s * 2 + b) * G3];
            xr = xp[d]; xz = xp[DD + d]; xn = xp[2 * DD + d];
        }

        const float* hb = &h_sm[b * DD];
        float a0 = 0.f, a1 = 0.f, a2 = 0.f;
#pragma unroll
        for (int k = 0; k < 16; k++) {
            float hv2 = hb[lane * 16 + k];
            a0 = fmaf(hv2, Wr[lane * 16 + k], a0);
            a1 = fmaf(hv2, Wz[lane * 16 + k], a1);
            a2 = fmaf(hv2, Wn[lane * 16 + k], a2);
        }
#pragma unroll
        for (int off = 16; off > 0; off >>= 1) {
            a0 += __shfl_down_sync(0xffffffffu, a0, off);
            a1 += __shfl_down_sync(0xffffffffu, a1, off);
            a2 += __shfl_down_sync(0xffffffffu, a2, off);
        }
        if (lane == 0) {
            float r = 1.f / (1.f + expf(-(xr + a0 + bh_r)));
            float z = 1.f / (1.f + expf(-(xz + a1 + bh_z)));
            float n = tanhf(xn + r * (a2 + bh_n));
            float hold = hb[d];
            float hn = (1.f - z) * n + z * hold;
            d_h[(s + 1) & 1][b * DD + d] = hn;
            d_gru[(size_t)(b * SS + s) * DD + d] = hn;
        }
        __threadfence();
        __syncthreads();
        if (t == 0) atomicAdd(&d_bar, 1u);
    }
}

// =====================================================================
// K4: Q/K projection: C = gru @ W^T  (M=2048, N=512, K=512)
// =====================================================================
template <int SEL>
__global__ void k_qk(const float* __restrict__ W)
{
    const int m0 = blockIdx.y * 64;
    const int n0 = blockIdx.x * 64;
    __shared__ float As[16][64];
    __shared__ float Bs[16][64];
    const int t = threadIdx.x;
    const int lrow = t >> 2, lk4 = (t & 3) * 4;
    const int ty = t >> 4, tx = t & 15;
    float acc[4][4];
#pragma unroll
    for (int i = 0; i < 4; i++)
#pragma unroll
        for (int j = 0; j < 4; j++) acc[i][j] = 0.f;

    for (int k0 = 0; k0 < DD; k0 += 16) {
        float4 a = *(const float4*)&d_gru[(size_t)(m0 + lrow) * DD + k0 + lk4];
        float4 bv = *(const float4*)&W[(size_t)(n0 + lrow) * DD + k0 + lk4];
        As[lk4 + 0][lrow] = a.x; As[lk4 + 1][lrow] = a.y;
        As[lk4 + 2][lrow] = a.z; As[lk4 + 3][lrow] = a.w;
        Bs[lk4 + 0][lrow] = bv.x; Bs[lk4 + 1][lrow] = bv.y;
        Bs[lk4 + 2][lrow] = bv.z; Bs[lk4 + 3][lrow] = bv.w;
        __syncthreads();
#pragma unroll
        for (int kk = 0; kk < 16; kk++) {
            float4 av = *(float4*)&As[kk][ty * 4];
            float4 bv2 = *(float4*)&Bs[kk][tx * 4];
            float a2[4] = {av.x, av.y, av.z, av.w};
            float b2[4] = {bv2.x, bv2.y, bv2.z, bv2.w};
#pragma unroll
            for (int i = 0; i < 4; i++)
#pragma unroll
                for (int j = 0; j < 4; j++) acc[i][j] += a2[i] * b2[j];
        }
        __syncthreads();
    }
    float* C = SEL ? d_Kc : d_Q;
#pragma unroll
    for (int i = 0; i < 4; i++)
#pragma unroll
        for (int j = 0; j < 4; j++)
            C[(size_t)(m0 + ty * 4 + i) * DD + n0 + tx * 4 + j] = acc[i][j];
}

// =====================================================================
// K5: RoPE in place on Q and K
// =====================================================================
__global__ void k_rope()
{
    int m = blockIdx.x;
    int i = threadIdx.x;            // pair index 0..255
    int s = m & (SS - 1);
    float invf = powf(10000.f, -((float)(2 * i) / (float)DD));
    float ang = (float)s * invf;
    float sn, cs;
    sincosf(ang, &sn, &cs);
    size_t base = (size_t)m * DD + 2 * i;
    float q0 = d_Q[base], q1 = d_Q[base + 1];
    d_Q[base]     = q0 * cs - q1 * sn;
    d_Q[base + 1] = q1 * cs + q0 * sn;
    float k0 = d_Kc[base], k1 = d_Kc[base + 1];
    d_Kc[base]     = k0 * cs - k1 * sn;
    d_Kc[base + 1] = k1 * cs + k0 * sn;
}

// =====================================================================
// K6: scores = Q K^T / sqrt(D) with causal mask (per batch z)
// =====================================================================
__global__ void k_scores()
{
    const int z = blockIdx.z;
    const int m0 = blockIdx.y * 64;   // i
    const int n0 = blockIdx.x * 64;   // j
    const int t = threadIdx.x;
    float* C = d_probs + (size_t)z * SS * SS;

    if (n0 >= m0 + 64) {   // tile fully masked
        for (int e = t; e < 64 * 64; e += 256) {
            int i = e >> 6, j = e & 63;
            C[(size_t)(m0 + i) * SS + n0 + j] = -1e30f;
        }
        return;
    }

    const float* A = d_Q + (size_t)z * SS * DD;
    const float* Bm = d_Kc + (size_t)z * SS * DD;
    __shared__ float As[16][64];
    __shared__ float Bs[16][64];
    const int lrow = t >> 2, lk4 = (t & 3) * 4;
    const int ty = t >> 4, tx = t & 15;
    float acc[4][4];
#pragma unroll
    for (int i = 0; i < 4; i++)
#pragma unroll
        for (int j = 0; j < 4; j++) acc[i][j] = 0.f;

    for (int k0 = 0; k0 < DD; k0 += 16) {
        float4 a = *(const float4*)&A[(size_t)(m0 + lrow) * DD + k0 + lk4];
        float4 bv = *(const float4*)&Bm[(size_t)(n0 + lrow) * DD + k0 + lk4];
        As[lk4 + 0][lrow] = a.x; As[lk4 + 1][lrow] = a.y;
        As[lk4 + 2][lrow] = a.z; As[lk4 + 3][lrow] = a.w;
        Bs[lk4 + 0][lrow] = bv.x; Bs[lk4 + 1][lrow] = bv.y;
        Bs[lk4 + 2][lrow] = bv.z; Bs[lk4 + 3][lrow] = bv.w;
        __syncthreads();
#pragma unroll
        for (int kk = 0; kk < 16; kk++) {
            float4 av = *(float4*)&As[kk][ty * 4];
            float4 bv2 = *(float4*)&Bs[kk][tx * 4];
            float a2[4] = {av.x, av.y, av.z, av.w};
            float b2[4] = {bv2.x, bv2.y, bv2.z, bv2.w};
#pragma unroll
            for (int i = 0; i < 4; i++)
#pragma unroll
                for (int j = 0; j < 4; j++) acc[i][j] += a2[i] * b2[j];
        }
        __syncthreads();
    }
    const float scale = 0.04419417382415922f;  // 1/sqrt(512)
#pragma unroll
    for (int i = 0; i < 4; i++) {
        int gi = m0 + ty * 4 + i;
#pragma unroll
        for (int j = 0; j < 4; j++) {
            int gj = n0 + tx * 4 + j;
            float v = acc[i][j] * scale;
            if (gj > gi) v = -1e30f;
            C[(size_t)gi * SS + gj] = v;
        }
    }
}

// =====================================================================
// K7: row softmax over 1024 (in place in d_probs)
// =====================================================================
__global__ void k_softmax_rows()
{
    int m = blockIdx.x;
    float* row = d_probs + (size_t)m * SS;
    const int t = threadIdx.x;
    __shared__ float red[256];

    float4 lv = *(float4*)&row[t * 4];
    float mx = fmaxf(fmaxf(lv.x, lv.y), fmaxf(lv.z, lv.w));
    red[t] = mx;
    __syncthreads();
    for (int off = 128; off > 0; off >>= 1) {
        if (t < off) red[t] = fmaxf(red[t], red[t + off]);
        __syncthreads();
    }
    mx = red[0];
    __syncthreads();

    float4 e;
    e.x = expf(lv.x - mx); e.y = expf(lv.y - mx);
    e.z = expf(lv.z - mx); e.w = expf(lv.w - mx);
    red[t] = e.x + e.y + e.z + e.w;
    __syncthreads();
    for (int off = 128; off > 0; off >>= 1) {
        if (t < off) red[t] += red[t + off];
        __syncthreads();
    }
    float inv = 1.f / red[0];
    e.x *= inv; e.y *= inv; e.z *= inv; e.w *= inv;
    *(float4*)&row[t * 4] = e;
}

// =====================================================================
// K8: context = probs @ gru  (per batch z): M=1024,N=512,K=1024
// =====================================================================
__global__ void k_ctx()
{
    const int z = blockIdx.z;
    const int m0 = blockIdx.y * 64;
    const int n0 = blockIdx.x * 64;
    const float* A = d_probs + (size_t)z * SS * SS;     // lda = 1024
    const float* Bm = d_gru + (size_t)z * SS * DD;      // [k][n], ldb = 512
    float* C = d_ctx + (size_t)z * SS * DD;

    __shared__ float As[16][64];
    __shared__ float Bs[16][64];
    const int t = threadIdx.x;
    const int lrow = t >> 2, lk4 = (t & 3) * 4;   // for A
    const int bk = t >> 4, bn4 = (t & 15) * 4;    // for B
    const int ty = t >> 4, tx = t & 15;
    float acc[4][4];
#pragma unroll
    for (int i = 0; i < 4; i++)
#pragma unroll
        for (int j = 0; j < 4; j++) acc[i][j] = 0.f;

    for (int k0 = 0; k0 < SS; k0 += 16) {
        float4 a = *(const float4*)&A[(size_t)(m0 + lrow) * SS + k0 + lk4];
        As[lk4 + 0][lrow] = a.x; As[lk4 + 1][lrow] = a.y;
        As[lk4 + 2][lrow] = a.z; As[lk4 + 3][lrow] = a.w;
        float4 bv = *(const float4*)&Bm[(size_t)(k0 + bk) * DD + n0 + bn4];
        *(float4*)&Bs[bk][bn4] = bv;
        __syncthreads();
#pragma unroll
        for (int kk = 0; kk < 16; kk++) {
            float4 av = *(float4*)&As[kk][ty * 4];
            float4 bv2 = *(float4*)&Bs[kk][tx * 4];
            float a2[4] = {av.x, av.y, av.z, av.w};
            float b2[4] = {bv2.x, bv2.y, bv2.z, bv2.w};
#pragma unroll
            for (int i = 0; i < 4; i++)
#pragma unroll
                for (int j = 0; j < 4; j++) acc[i][j] += a2[i] * b2[j];
        }
        __syncthreads();
    }
#pragma unroll
    for (int i = 0; i < 4; i++)
#pragma unroll
        for (int j = 0; j < 4; j++)
            C[(size_t)(m0 + ty * 4 + i) * DD + n0 + tx * 4 + j] = acc[i][j];
}

// =====================================================================
// K9: combined = [gru, ctx]; gate = sigmoid(combined . gate_W + gate_b)
// =====================================================================
__global__ void k_comb_gate(const float* __restrict__ gate_W,
                            const float* __restrict__ gate_b)
{
    int m = blockIdx.x;
    int t = threadIdx.x;
    __shared__ float red[256];
    float acc = 0.f;
    for (int idx = t; idx < DD; idx += 256) {
        float g = d_gru[(size_t)m * DD + idx];
        float c = d_ctx[(size_t)m * DD + idx];
        d_comb[(size_t)m * 2 * DD + idx] = g;
        d_comb[(size_t)m * 2 * DD + DD + idx] = c;
        acc += g * gate_W[idx] + c * gate_W[DD + idx];
    }
    red[t] = acc;
    __syncthreads();
    for (int off = 128; off > 0; off >>= 1) {
        if (t < off) red[t] += red[t + off];
        __syncthreads();
    }
    if (t == 0) d_gate[m] = 1.f / (1.f + expf(-(red[0] + gate_b[0])));
}

// =====================================================================
// K10: gen logits GEMM 128x128x8, 8x8 microtile.
// C[2048,32000] = comb[2048,1024] @ gen_W[32000,1024]^T + gen_b
// =====================================================================
__global__ void __launch_bounds__(256) k_gen128(const float* __restrict__ Bw,
                                                const float* __restrict__ bias)
{
    const int m0 = blockIdx.y * 128;
    const int n0 = blockIdx.x * 128;
    __shared__ float As[8][128];
    __shared__ float Bs[8][128];
    const int t = threadIdx.x;
    const int lrow = t >> 1;
    const int lk = (t & 1) * 4;
    const int ty = t >> 4, tx = t & 15;
    float acc[8][8];
#pragma unroll
    for (int i = 0; i < 8; i++)
#pragma unroll
        for (int j = 0; j < 8; j++) acc[i][j] = 0.f;

    for (int k0 = 0; k0 < 2 * DD; k0 += 8) {
        float4 a = *(const float4*)&d_comb[(size_t)(m0 + lrow) * (2 * DD) + k0 + lk];
        float4 b = *(const float4*)&Bw[(size_t)(n0 + lrow) * (2 * DD) + k0 + lk];
        As[lk + 0][lrow] = a.x; As[lk + 1][lrow] = a.y;
        As[lk + 2][lrow] = a.z; As[lk + 3][lrow] = a.w;
        Bs[lk + 0][lrow] = b.x; Bs[lk + 1][lrow] = b.y;
        Bs[lk + 2][lrow] = b.z; Bs[lk + 3][lrow] = b.w;
        __syncthreads();
#pragma unroll
        for (int kk = 0; kk < 8; kk++) {
            float4 a0 = *(float4*)&As[kk][ty * 8];
            float4 a1 = *(float4*)&As[kk][ty * 8 + 4];
            float4 b0 = *(float4*)&Bs[kk][tx * 8];
            float4 b1 = *(float4*)&Bs[kk][tx * 8 + 4];
            float ar[8] = {a0.x, a0.y, a0.z, a0.w, a1.x, a1.y, a1.z, a1.w};
            float br[8] = {b0.x, b0.y, b0.z, b0.w, b1.x, b1.y, b1.z, b1.w};
#pragma unroll
            for (int i = 0; i < 8; i++)
#pragma unroll
                for (int j = 0; j < 8; j++) acc[i][j] = fmaf(ar[i], br[j], acc[i][j]);
        }
        __syncthreads();
    }
#pragma unroll
    for (int i = 0; i < 8; i++) {
        size_t row = (size_t)(m0 + ty * 8 + i);
#pragma unroll
        for (int j = 0; j < 8; j++) {
            int n = n0 + tx * 8 + j;
            d_logits[row * VV + n] = acc[i][j] + bias[n];
        }
    }
}

// =====================================================================
// K11: per-row online max+sumexp over V
// =====================================================================
__global__ void k_rowstats()
{
    int m = blockIdx.x;
    const float* row = d_logits + (size_t)m * VV;
    const int t = threadIdx.x;
    float mx = -1e30f, sm = 0.f;
    for (int v4 = t; v4 < VV / 4; v4 += 256) {
        float4 l = *(const float4*)&row[v4 * 4];
        float vals[4] = {l.x, l.y, l.z, l.w};
#pragma unroll
        for (int u = 0; u < 4; u++) {
            float l1 = vals[u];
            if (l1 > mx) { sm = sm * __expf(mx - l1) + 1.f; mx = l1; }
            else sm += __expf(l1 - mx);
        }
    }
    __shared__ float smx[256], ssm[256];
    smx[t] = mx; ssm[t] = sm;
    for (int off = 128; off > 0; off >>= 1) {
        __syncthreads();
        if (t < off) {
            float m2 = smx[t + off], s2 = ssm[t + off];
            if (m2 > mx) { sm = sm * __expf(mx - m2) + s2; mx = m2; }
            else sm += s2 * __expf(m2 - mx);
            smx[t] = mx; ssm[t] = sm;
        }
    }
    if (t == 0) { d_rowmax[m] = mx; d_rowsum[m] = sm; }
}

// =====================================================================
// K12: out = gate * softmax(logits)
// =====================================================================
__global__ void k_blend(float* __restrict__ out)
{
    size_t idx4 = (size_t)blockIdx.x * 256 + threadIdx.x;
    int m = (int)(idx4 / (VV / 4));
    float4 l = *(const float4*)&d_logits[idx4 * 4];
    float g = d_gate[m];
    float mx = d_rowmax[m];
    float is = g / d_rowsum[m];
    float4 o;
    o.x = __expf(l.x - mx) * is;
    o.y = __expf(l.y - mx) * is;
    o.z = __expf(l.z - mx) * is;
    o.w = __expf(l.w - mx) * is;
    *(float4*)&out[idx4 * 4] = o;
}

// =====================================================================
// K13: scatter copy-probs: out[m, x[b,j]] += (1-gate[m]) * probs[m,j], j<=i
// =====================================================================
__global__ void k_scatter(const int* __restrict__ x, float* __restrict__ out)
{
    int m = blockIdx.x;
    int b = m >> 10;
    int i = m & (SS - 1);
    float om = 1.f - d_gate[m];
    const float* pr = d_probs + (size_t)m * SS;
    float* orow = out + (size_t)m * VV;
    for (int j = threadIdx.x; j <= i; j += 256) {
        atomicAdd(&orow[x[b * SS + j]], om * pr[j]);
    }
}

// =====================================================================
// launch
// =====================================================================
extern "C" void kernel_launch(void* const* d_in, const int* in_sizes, int n_in,
                              void* d_out, int out_size)
{
    const int*   x        = (const int*)d_in[0];
    const float* tok_emb  = (const float*)d_in[1];
    const float* pos_emb  = (const float*)d_in[2];
    const float* W_ih     = (const float*)d_in[3];
    const float* W_hh     = (const float*)d_in[4];
    const float* b_ih     = (const float*)d_in[5];
    const float* b_hh     = (const float*)d_in[6];
    const float* W_q      = (const float*)d_in[7];
    const float* W_k      = (const float*)d_in[8];
    const float* gen_W    = (const float*)d_in[9];
    const float* gen_b    = (const float*)d_in[10];
    const float* gate_W   = (const float*)d_in[11];
    const float* gate_b   = (const float*)d_in[12];
    float* out = (float*)d_out;

    k_xproj<<<dim3(G3 / 64, MM / 64), 256>>>(x, tok_emb, pos_emb, W_ih, b_ih);
    k_init<<<1, 256>>>();
    k_gru<<<GRU_CTAS, 256>>>(W_hh, b_hh);
    k_qk<0><<<dim3(DD / 64, MM / 64), 256>>>(W_q);
    k_qk<1><<<dim3(DD / 64, MM / 64), 256>>>(W_k);
    k_rope<<<MM, 256>>>();
    k_scores<<<dim3(SS / 64, SS / 64, BB), 256>>>();
    k_softmax_rows<<<MM, 256>>>();
    k_ctx<<<dim3(DD / 64, SS / 64, BB), 256>>>();
    k_comb_gate<<<MM, 256>>>(gate_W, gate_b);
    k_gen128<<<dim3(VV / 128, MM / 128), 256>>>(gen_W, gen_b);
    k_rowstats<<<MM, 256>>>();
    k_blend<<<(MM * (VV / 4)) / 256, 256>>>(out);
    k_scatter<<<MM, 256>>>(x, out);
}

// round 2
// speedup vs baseline: 1.7184x; 1.7184x over previous
#include <cuda_runtime.h>
#include <cuda_bf16.h>
#include <math.h>
#include <stdint.h>

// Problem constants
#define BB 2
#define SS 1024
#define DD 512
#define VV 32000
#define MM 2048          // BB*SS rows
#define G3 1536          // 3*DD
#define GRU_CTAS 128

// ---------------- scratch (device globals; no runtime allocation) ----------------
__device__ float d_xproj[MM * G3];           // [s*2+b][1536]
__device__ float d_gru[MM * DD];             // [b*1024+s][512]
__device__ float d_h[2][BB * DD];            // ping-pong hidden state
__device__ unsigned d_bar;                   // grid barrier counter
__device__ float d_Q[MM * DD];
__device__ float d_Kc[MM * DD];
__device__ float d_probs[BB * SS * SS];      // scores -> probs (in place)
__device__ float d_ctx[MM * DD];
__device__ __nv_bfloat16 d_comb_bf[MM * 2 * DD];      // bf16 combined
__device__ __nv_bfloat16 d_genW_bf[(size_t)VV * 2 * DD]; // bf16 gen_W
__device__ float d_gate[MM];
__device__ float d_logits[65536000];         // 2048*32000
__device__ float d_rowmax[MM];
__device__ float d_rowsum[MM];

// =====================================================================
// K1: x_emb gather + x_proj = x_emb @ W_ih^T + b_ih   (64x64x16 tiles)
// =====================================================================
__global__ void k_xproj(const int* __restrict__ x,
                        const float* __restrict__ tok_emb,
                        const float* __restrict__ pos_emb,
                        const float* __restrict__ W_ih,
                        const float* __restrict__ b_ih)
{
    const int m0 = blockIdx.y * 64;
    const int n0 = blockIdx.x * 64;
    __shared__ float As[16][64];
    __shared__ float Bs[16][64];
    __shared__ int tokS[64];
    __shared__ int sS[64];

    const int t = threadIdx.x;
    if (t < 64) {
        int m = m0 + t;
        int b = m & 1, s = m >> 1;
        tokS[t] = x[b * SS + s];
        sS[t] = s;
    }
    __syncthreads();

    const int lrow = t >> 2;
    const int lk4  = (t & 3) * 4;
    const int ty = t >> 4, tx = t & 15;
    float acc[4][4];
#pragma unroll
    for (int i = 0; i < 4; i++)
#pragma unroll
        for (int j = 0; j < 4; j++) acc[i][j] = 0.f;

    for (int k0 = 0; k0 < DD; k0 += 16) {
        float4 te = *(const float4*)&tok_emb[(size_t)tokS[lrow] * DD + k0 + lk4];
        float4 pe = *(const float4*)&pos_emb[(size_t)sS[lrow] * DD + k0 + lk4];
        float4 bv = *(const float4*)&W_ih[(size_t)(n0 + lrow) * DD + k0 + lk4];
        As[lk4 + 0][lrow] = te.x + pe.x;
        As[lk4 + 1][lrow] = te.y + pe.y;
        As[lk4 + 2][lrow] = te.z + pe.z;
        As[lk4 + 3][lrow] = te.w + pe.w;
        Bs[lk4 + 0][lrow] = bv.x;
        Bs[lk4 + 1][lrow] = bv.y;
        Bs[lk4 + 2][lrow] = bv.z;
        Bs[lk4 + 3][lrow] = bv.w;
        __syncthreads();
#pragma unroll
        for (int kk = 0; kk < 16; kk++) {
            float4 av = *(float4*)&As[kk][ty * 4];
            float4 bv2 = *(float4*)&Bs[kk][tx * 4];
            float a[4] = {av.x, av.y, av.z, av.w};
            float b2[4] = {bv2.x, bv2.y, bv2.z, bv2.w};
#pragma unroll
            for (int i = 0; i < 4; i++)
#pragma unroll
                for (int j = 0; j < 4; j++) acc[i][j] += a[i] * b2[j];
        }
        __syncthreads();
    }
#pragma unroll
    for (int i = 0; i < 4; i++) {
        int m = m0 + ty * 4 + i;
#pragma unroll
        for (int j = 0; j < 4; j++) {
            int n = n0 + tx * 4 + j;
            d_xproj[(size_t)m * G3 + n] = acc[i][j] + b_ih[n];
        }
    }
}

// =====================================================================
// K2: init barrier + h0
// =====================================================================
__global__ void k_init()
{
    int t = threadIdx.x;
    for (int i = t; i < 2 * BB * DD; i += blockDim.x) ((float*)d_h)[i] = 0.f;
    if (t == 0) d_bar = 0u;
}

// =====================================================================
// K2b: convert gen_W to bf16
// =====================================================================
__global__ void k_convW(const float* __restrict__ W)
{
    size_t i = ((size_t)blockIdx.x * 256 + threadIdx.x) * 8;
    float4 f0 = *(const float4*)&W[i];
    float4 f1 = *(const float4*)&W[i + 4];
    __nv_bfloat16 h[8];
    h[0] = __float2bfloat16(f0.x); h[1] = __float2bfloat16(f0.y);
    h[2] = __float2bfloat16(f0.z); h[3] = __float2bfloat16(f0.w);
    h[4] = __float2bfloat16(f1.x); h[5] = __float2bfloat16(f1.y);
    h[6] = __float2bfloat16(f1.z); h[7] = __float2bfloat16(f1.w);
    *(uint4*)&d_genW_bf[i] = *(uint4*)h;
}

// =====================================================================
// K3: GRU recurrence. 128 persistent CTAs, each owns 4 hidden dims.
// =====================================================================
__global__ void k_gru(const float* __restrict__ W_hh,
                      const float* __restrict__ b_hh)
{
    __shared__ float Wsm[4 * 3 * DD];   // 24KB
    __shared__ float h_sm[BB * DD];     // 4KB

    const int t = threadIdx.x;
    const int c = blockIdx.x;
    const int d_base = c * 4;

    for (int i = t; i < 1536; i += 256) {
        int fi = i * 4;
        int dl = fi / 1536;
        int rem = fi - dl * 1536;
        int g = rem / 512;
        int k = rem & 511;
        *(float4*)&Wsm[fi] =
            *(const float4*)&W_hh[(size_t)(g * DD + d_base + dl) * DD + k];
    }

    const int w = t >> 5, lane = t & 31;
    const int b = w & 1, dl = w >> 1;
    const int d = d_base + dl;
    const float bh_r = b_hh[d];
    const float bh_z = b_hh[DD + d];
    const float bh_n = b_hh[2 * DD + d];
    const float* Wr = &Wsm[(dl * 3 + 0) * DD];
    const float* Wz = &Wsm[(dl * 3 + 1) * DD];
    const float* Wn = &Wsm[(dl * 3 + 2) * DD];
    __syncthreads();

    for (int s = 0; s < SS; ++s) {
        if (s > 0 && t == 0) {
            unsigned target = (unsigned)GRU_CTAS * (unsigned)s;
            while (*(volatile unsigned*)&d_bar < target) {}
        }
        __syncthreads();

        float4 hv = __ldcv((const float4*)&d_h[s & 1][0] + t);
        *(float4*)&h_sm[t * 4] = hv;
        __syncthreads();

        float xr = 0.f, xz = 0.f, xn = 0.f;
        if (lane == 0) {
            const float* xp = &d_xproj[(size_t)(s * 2 + b) * G3];
            xr = xp[d]; xz = xp[DD + d]; xn = xp[2 * DD + d];
        }

        const float* hb = &h_sm[b * DD];
        float a0 = 0.f, a1 = 0.f, a2 = 0.f;
#pragma unroll
        for (int k = 0; k < 16; k++) {
            float hv2 = hb[lane * 16 + k];
            a0 = fmaf(hv2, Wr[lane * 16 + k], a0);
            a1 = fmaf(hv2, Wz[lane * 16 + k], a1);
            a2 = fmaf(hv2, Wn[lane * 16 + k], a2);
        }
#pragma unroll
        for (int off = 16; off > 0; off >>= 1) {
            a0 += __shfl_down_sync(0xffffffffu, a0, off);
            a1 += __shfl_down_sync(0xffffffffu, a1, off);
            a2 += __shfl_down_sync(0xffffffffu, a2, off);
        }
        if (lane == 0) {
            float r = 1.f / (1.f + expf(-(xr + a0 + bh_r)));
            float z = 1.f / (1.f + expf(-(xz + a1 + bh_z)));
            float n = tanhf(xn + r * (a2 + bh_n));
            float hold = hb[d];
            float hn = (1.f - z) * n + z * hold;
            d_h[(s + 1) & 1][b * DD + d] = hn;
            d_gru[(size_t)(b * SS + s) * DD + d] = hn;
        }
        __threadfence();
        __syncthreads();
        if (t == 0) atomicAdd(&d_bar, 1u);
    }
}

// =====================================================================
// K4: Q/K projection
// =====================================================================
template <int SEL>
__global__ void k_qk(const float* __restrict__ W)
{
    const int m0 = blockIdx.y * 64;
    const int n0 = blockIdx.x * 64;
    __shared__ float As[16][64];
    __shared__ float Bs[16][64];
    const int t = threadIdx.x;
    const int lrow = t >> 2, lk4 = (t & 3) * 4;
    const int ty = t >> 4, tx = t & 15;
    float acc[4][4];
#pragma unroll
    for (int i = 0; i < 4; i++)
#pragma unroll
        for (int j = 0; j < 4; j++) acc[i][j] = 0.f;

    for (int k0 = 0; k0 < DD; k0 += 16) {
        float4 a = *(const float4*)&d_gru[(size_t)(m0 + lrow) * DD + k0 + lk4];
        float4 bv = *(const float4*)&W[(size_t)(n0 + lrow) * DD + k0 + lk4];
        As[lk4 + 0][lrow] = a.x; As[lk4 + 1][lrow] = a.y;
        As[lk4 + 2][lrow] = a.z; As[lk4 + 3][lrow] = a.w;
        Bs[lk4 + 0][lrow] = bv.x; Bs[lk4 + 1][lrow] = bv.y;
        Bs[lk4 + 2][lrow] = bv.z; Bs[lk4 + 3][lrow] = bv.w;
        __syncthreads();
#pragma unroll
        for (int kk = 0; kk < 16; kk++) {
            float4 av = *(float4*)&As[kk][ty * 4];
            float4 bv2 = *(float4*)&Bs[kk][tx * 4];
            float a2[4] = {av.x, av.y, av.z, av.w};
            float b2[4] = {bv2.x, bv2.y, bv2.z, bv2.w};
#pragma unroll
            for (int i = 0; i < 4; i++)
#pragma unroll
                for (int j = 0; j < 4; j++) acc[i][j] += a2[i] * b2[j];
        }
        __syncthreads();
    }
    float* C = SEL ? d_Kc : d_Q;
#pragma unroll
    for (int i = 0; i < 4; i++)
#pragma unroll
        for (int j = 0; j < 4; j++)
            C[(size_t)(m0 + ty * 4 + i) * DD + n0 + tx * 4 + j] = acc[i][j];
}

// =====================================================================
// K5: RoPE in place on Q and K
// =====================================================================
__global__ void k_rope()
{
    int m = blockIdx.x;
    int i = threadIdx.x;
    int s = m & (SS - 1);
    float invf = powf(10000.f, -((float)(2 * i) / (float)DD));
    float ang = (float)s * invf;
    float sn, cs;
    sincosf(ang, &sn, &cs);
    size_t base = (size_t)m * DD + 2 * i;
    float q0 = d_Q[base], q1 = d_Q[base + 1];
    d_Q[base]     = q0 * cs - q1 * sn;
    d_Q[base + 1] = q1 * cs + q0 * sn;
    float k0 = d_Kc[base], k1 = d_Kc[base + 1];
    d_Kc[base]     = k0 * cs - k1 * sn;
    d_Kc[base + 1] = k1 * cs + k0 * sn;
}

// =====================================================================
// K6: scores = Q K^T / sqrt(D) with causal mask
// =====================================================================
__global__ void k_scores()
{
    const int z = blockIdx.z;
    const int m0 = blockIdx.y * 64;
    const int n0 = blockIdx.x * 64;
    const int t = threadIdx.x;
    float* C = d_probs + (size_t)z * SS * SS;

    if (n0 >= m0 + 64) {
        for (int e = t; e < 64 * 64; e += 256) {
            int i = e >> 6, j = e & 63;
            C[(size_t)(m0 + i) * SS + n0 + j] = -1e30f;
        }
        return;
    }

    const float* A = d_Q + (size_t)z * SS * DD;
    const float* Bm = d_Kc + (size_t)z * SS * DD;
    __shared__ float As[16][64];
    __shared__ float Bs[16][64];
    const int lrow = t >> 2, lk4 = (t & 3) * 4;
    const int ty = t >> 4, tx = t & 15;
    float acc[4][4];
#pragma unroll
    for (int i = 0; i < 4; i++)
#pragma unroll
        for (int j = 0; j < 4; j++) acc[i][j] = 0.f;

    for (int k0 = 0; k0 < DD; k0 += 16) {
        float4 a = *(const float4*)&A[(size_t)(m0 + lrow) * DD + k0 + lk4];
        float4 bv = *(const float4*)&Bm[(size_t)(n0 + lrow) * DD + k0 + lk4];
        As[lk4 + 0][lrow] = a.x; As[lk4 + 1][lrow] = a.y;
        As[lk4 + 2][lrow] = a.z; As[lk4 + 3][lrow] = a.w;
        Bs[lk4 + 0][lrow] = bv.x; Bs[lk4 + 1][lrow] = bv.y;
        Bs[lk4 + 2][lrow] = bv.z; Bs[lk4 + 3][lrow] = bv.w;
        __syncthreads();
#pragma unroll
        for (int kk = 0; kk < 16; kk++) {
            float4 av = *(float4*)&As[kk][ty * 4];
            float4 bv2 = *(float4*)&Bs[kk][tx * 4];
            float a2[4] = {av.x, av.y, av.z, av.w};
            float b2[4] = {bv2.x, bv2.y, bv2.z, bv2.w};
#pragma unroll
            for (int i = 0; i < 4; i++)
#pragma unroll
                for (int j = 0; j < 4; j++) acc[i][j] += a2[i] * b2[j];
        }
        __syncthreads();
    }
    const float scale = 0.04419417382415922f;
#pragma unroll
    for (int i = 0; i < 4; i++) {
        int gi = m0 + ty * 4 + i;
#pragma unroll
        for (int j = 0; j < 4; j++) {
            int gj = n0 + tx * 4 + j;
            float v = acc[i][j] * scale;
            if (gj > gi) v = -1e30f;
            C[(size_t)gi * SS + gj] = v;
        }
    }
}

// =====================================================================
// K7: row softmax over 1024
// =====================================================================
__global__ void k_softmax_rows()
{
    int m = blockIdx.x;
    float* row = d_probs + (size_t)m * SS;
    const int t = threadIdx.x;
    __shared__ float red[256];

    float4 lv = *(float4*)&row[t * 4];
    float mx = fmaxf(fmaxf(lv.x, lv.y), fmaxf(lv.z, lv.w));
    red[t] = mx;
    __syncthreads();
    for (int off = 128; off > 0; off >>= 1) {
        if (t < off) red[t] = fmaxf(red[t], red[t + off]);
        __syncthreads();
    }
    mx = red[0];
    __syncthreads();

    float4 e;
    e.x = expf(lv.x - mx); e.y = expf(lv.y - mx);
    e.z = expf(lv.z - mx); e.w = expf(lv.w - mx);
    red[t] = e.x + e.y + e.z + e.w;
    __syncthreads();
    for (int off = 128; off > 0; off >>= 1) {
        if (t < off) red[t] += red[t + off];
        __syncthreads();
    }
    float inv = 1.f / red[0];
    e.x *= inv; e.y *= inv; e.z *= inv; e.w *= inv;
    *(float4*)&row[t * 4] = e;
}

// =====================================================================
// K8: context = probs @ gru
// =====================================================================
__global__ void k_ctx()
{
    const int z = blockIdx.z;
    const int m0 = blockIdx.y * 64;
    const int n0 = blockIdx.x * 64;
    const float* A = d_probs + (size_t)z * SS * SS;
    const float* Bm = d_gru + (size_t)z * SS * DD;
    float* C = d_ctx + (size_t)z * SS * DD;

    __shared__ float As[16][64];
    __shared__ float Bs[16][64];
    const int t = threadIdx.x;
    const int lrow = t >> 2, lk4 = (t & 3) * 4;
    const int bk = t >> 4, bn4 = (t & 15) * 4;
    const int ty = t >> 4, tx = t & 15;
    float acc[4][4];
#pragma unroll
    for (int i = 0; i < 4; i++)
#pragma unroll
        for (int j = 0; j < 4; j++) acc[i][j] = 0.f;

    for (int k0 = 0; k0 < SS; k0 += 16) {
        float4 a = *(const float4*)&A[(size_t)(m0 + lrow) * SS + k0 + lk4];
        As[lk4 + 0][lrow] = a.x; As[lk4 + 1][lrow] = a.y;
        As[lk4 + 2][lrow] = a.z; As[lk4 + 3][lrow] = a.w;
        float4 bv = *(const float4*)&Bm[(size_t)(k0 + bk) * DD + n0 + bn4];
        *(float4*)&Bs[bk][bn4] = bv;
        __syncthreads();
#pragma unroll
        for (int kk = 0; kk < 16; kk++) {
            float4 av = *(float4*)&As[kk][ty * 4];
            float4 bv2 = *(float4*)&Bs[kk][tx * 4];
            float a2[4] = {av.x, av.y, av.z, av.w};
            float b2[4] = {bv2.x, bv2.y, bv2.z, bv2.w};
#pragma unroll
            for (int i = 0; i < 4; i++)
#pragma unroll
                for (int j = 0; j < 4; j++) acc[i][j] += a2[i] * b2[j];
        }
        __syncthreads();
    }
#pragma unroll
    for (int i = 0; i < 4; i++)
#pragma unroll
        for (int j = 0; j < 4; j++)
            C[(size_t)(m0 + ty * 4 + i) * DD + n0 + tx * 4 + j] = acc[i][j];
}

// =====================================================================
// K9: combined (bf16) = [gru, ctx]; gate = sigmoid(combined . gate_W + b)
// =====================================================================
__global__ void k_comb_gate(const float* __restrict__ gate_W,
                            const float* __restrict__ gate_b)
{
    int m = blockIdx.x;
    int t = threadIdx.x;
    __shared__ float red[256];
    float acc = 0.f;
    for (int idx = t; idx < DD; idx += 256) {
        float g = d_gru[(size_t)m * DD + idx];
        float c = d_ctx[(size_t)m * DD + idx];
        d_comb_bf[(size_t)m * 2 * DD + idx] = __float2bfloat16(g);
        d_comb_bf[(size_t)m * 2 * DD + DD + idx] = __float2bfloat16(c);
        acc += g * gate_W[idx] + c * gate_W[DD + idx];
    }
    red[t] = acc;
    __syncthreads();
    for (int off = 128; off > 0; off >>= 1) {
        if (t < off) red[t] += red[t + off];
        __syncthreads();
    }
    if (t == 0) d_gate[m] = 1.f / (1.f + expf(-(red[0] + gate_b[0])));
}

// =====================================================================
// K10: gen logits GEMM via mma.sync bf16 (tensor cores)
// C[2048,32000] = comb_bf[2048,1024] @ genW_bf[32000,1024]^T + gen_b
// CTA tile 128x128, K-chunk 64. 8 warps = 2(M) x 4(N), warp tile 64x32.
// =====================================================================
__device__ __forceinline__ void mma_bf16(float& c0, float& c1, float& c2, float& c3,
                                         uint32_t a0, uint32_t a1, uint32_t a2, uint32_t a3,
                                         uint32_t b0, uint32_t b1)
{
    asm volatile(
        "mma.sync.aligned.m16n8k16.row.col.f32.bf16.bf16.f32 "
        "{%0,%1,%2,%3}, {%4,%5,%6,%7}, {%8,%9}, {%0,%1,%2,%3};\n"
        : "+f"(c0), "+f"(c1), "+f"(c2), "+f"(c3)
        : "r"(a0), "r"(a1), "r"(a2), "r"(a3), "r"(b0), "r"(b1));
}

__global__ void __launch_bounds__(256) k_gen_mma(const float* __restrict__ bias)
{
    const int n0 = blockIdx.x * 128;
    const int m0 = blockIdx.y * 128;
    __shared__ __nv_bfloat16 As[128][72];   // 18KB, padded: 36-word row stride
    __shared__ __nv_bfloat16 Bs[128][72];

    const int t = threadIdx.x;
    const int w = t >> 5, lane = t & 31;
    const int wm = (w >> 2) * 64;           // warp M offset in tile
    const int wn = (w & 3) * 32;            // warp N offset in tile
    const int g = lane >> 2, q = lane & 3;

    float acc[4][4][4];
#pragma unroll
    for (int i = 0; i < 4; i++)
#pragma unroll
        for (int j = 0; j < 4; j++)
#pragma unroll
            for (int r = 0; r < 4; r++) acc[i][j][r] = 0.f;

    for (int k0 = 0; k0 < 2 * DD; k0 += 64) {
        // stage tiles: 128 rows x 64 cols bf16 each, 8 bf16 per thread per iter
#pragma unroll
        for (int it = 0; it < 4; it++) {
            int idx = it * 256 + t;
            int row = idx >> 3;
            int c8 = (idx & 7) * 8;
            *(uint4*)&As[row][c8] =
                *(const uint4*)&d_comb_bf[(size_t)(m0 + row) * (2 * DD) + k0 + c8];
            *(uint4*)&Bs[row][c8] =
                *(const uint4*)&d_genW_bf[(size_t)(n0 + row) * (2 * DD) + k0 + c8];
        }
        __syncthreads();

#pragma unroll
        for (int kk = 0; kk < 64; kk += 16) {
            uint32_t af[4][4];
#pragma unroll
            for (int i = 0; i < 4; i++) {
                int r = wm + i * 16 + g;
                af[i][0] = *(const uint32_t*)&As[r][kk + q * 2];
                af[i][1] = *(const uint32_t*)&As[r + 8][kk + q * 2];
                af[i][2] = *(const uint32_t*)&As[r][kk + q * 2 + 8];
                af[i][3] = *(const uint32_t*)&As[r + 8][kk + q * 2 + 8];
            }
            uint32_t bfr[4][2];
#pragma unroll
            for (int j = 0; j < 4; j++) {
                int n = wn + j * 8 + g;
                bfr[j][0] = *(const uint32_t*)&Bs[n][kk + q * 2];
                bfr[j][1] = *(const uint32_t*)&Bs[n][kk + q * 2 + 8];
            }
#pragma unroll
            for (int i = 0; i < 4; i++)
#pragma unroll
                for (int j = 0; j < 4; j++)
                    mma_bf16(acc[i][j][0], acc[i][j][1], acc[i][j][2], acc[i][j][3],
                             af[i][0], af[i][1], af[i][2], af[i][3],
                             bfr[j][0], bfr[j][1]);
        }
        __syncthreads();
    }

    // epilogue: add bias, store
#pragma unroll
    for (int j = 0; j < 4; j++) {
        int n = n0 + wn + j * 8 + q * 2;
        float2 bv = *(const float2*)&bias[n];
#pragma unroll
        for (int i = 0; i < 4; i++) {
            size_t r0 = (size_t)(m0 + wm + i * 16 + g);
            size_t r1 = r0 + 8;
            float2 o0 = {acc[i][j][0] + bv.x, acc[i][j][1] + bv.y};
            float2 o1 = {acc[i][j][2] + bv.x, acc[i][j][3] + bv.y};
            *(float2*)&d_logits[r0 * VV + n] = o0;
            *(float2*)&d_logits[r1 * VV + n] = o1;
        }
    }
}

// =====================================================================
// K11: per-row online max+sumexp over V
// =====================================================================
__global__ void k_rowstats()
{
    int m = blockIdx.x;
    const float* row = d_logits + (size_t)m * VV;
    const int t = threadIdx.x;
    float mx = -1e30f, sm = 0.f;
    for (int v4 = t; v4 < VV / 4; v4 += 256) {
        float4 l = *(const float4*)&row[v4 * 4];
        float vals[4] = {l.x, l.y, l.z, l.w};
#pragma unroll
        for (int u = 0; u < 4; u++) {
            float l1 = vals[u];
            if (l1 > mx) { sm = sm * __expf(mx - l1) + 1.f; mx = l1; }
            else sm += __expf(l1 - mx);
        }
    }
    __shared__ float smx[256], ssm[256];
    smx[t] = mx; ssm[t] = sm;
    for (int off = 128; off > 0; off >>= 1) {
        __syncthreads();
        if (t < off) {
            float m2 = smx[t + off], s2 = ssm[t + off];
            if (m2 > mx) { sm = sm * __expf(mx - m2) + s2; mx = m2; }
            else sm += s2 * __expf(m2 - mx);
            smx[t] = mx; ssm[t] = sm;
        }
    }
    if (t == 0) { d_rowmax[m] = mx; d_rowsum[m] = sm; }
}

// =====================================================================
// K12: out = gate * softmax(logits)
// =====================================================================
__global__ void k_blend(float* __restrict__ out)
{
    size_t idx4 = (size_t)blockIdx.x * 256 + threadIdx.x;
    int m = (int)(idx4 / (VV / 4));
    float4 l = *(const float4*)&d_logits[idx4 * 4];
    float g = d_gate[m];
    float mx = d_rowmax[m];
    float is = g / d_rowsum[m];
    float4 o;
    o.x = __expf(l.x - mx) * is;
    o.y = __expf(l.y - mx) * is;
    o.z = __expf(l.z - mx) * is;
    o.w = __expf(l.w - mx) * is;
    *(float4*)&out[idx4 * 4] = o;
}

// =====================================================================
// K13: scatter copy-probs
// =====================================================================
__global__ void k_scatter(const int* __restrict__ x, float* __restrict__ out)
{
    int m = blockIdx.x;
    int b = m >> 10;
    int i = m & (SS - 1);
    float om = 1.f - d_gate[m];
    const float* pr = d_probs + (size_t)m * SS;
    float* orow = out + (size_t)m * VV;
    for (int j = threadIdx.x; j <= i; j += 256) {
        atomicAdd(&orow[x[b * SS + j]], om * pr[j]);
    }
}

// =====================================================================
// launch
// =====================================================================
extern "C" void kernel_launch(void* const* d_in, const int* in_sizes, int n_in,
                              void* d_out, int out_size)
{
    const int*   x        = (const int*)d_in[0];
    const float* tok_emb  = (const float*)d_in[1];
    const float* pos_emb  = (const float*)d_in[2];
    const float* W_ih     = (const float*)d_in[3];
    const float* W_hh     = (const float*)d_in[4];
    const float* b_ih     = (const float*)d_in[5];
    const float* b_hh     = (const float*)d_in[6];
    const float* W_q      = (const float*)d_in[7];
    const float* W_k      = (const float*)d_in[8];
    const float* gen_W    = (const float*)d_in[9];
    const float* gen_b    = (const float*)d_in[10];
    const float* gate_W   = (const float*)d_in[11];
    const float* gate_b   = (const float*)d_in[12];
    float* out = (float*)d_out;

    k_xproj<<<dim3(G3 / 64, MM / 64), 256>>>(x, tok_emb, pos_emb, W_ih, b_ih);
    k_init<<<1, 256>>>();
    k_convW<<<(VV * 2 * DD) / (8 * 256), 256>>>(gen_W);
    k_gru<<<GRU_CTAS, 256>>>(W_hh, b_hh);
    k_qk<0><<<dim3(DD / 64, MM / 64), 256>>>(W_q);
    k_qk<1><<<dim3(DD / 64, MM / 64), 256>>>(W_k);
    k_rope<<<MM, 256>>>();
    k_scores<<<dim3(SS / 64, SS / 64, BB), 256>>>();
    k_softmax_rows<<<MM, 256>>>();
    k_ctx<<<dim3(DD / 64, SS / 64, BB), 256>>>();
    k_comb_gate<<<MM, 256>>>(gate_W, gate_b);
    k_gen_mma<<<dim3(VV / 128, MM / 128), 256>>>(gen_b);
    k_rowstats<<<MM, 256>>>();
    k_blend<<<(MM * (VV / 4)) / 256, 256>>>(out);
    k_scatter<<<MM, 256>>>(x, out);
}

// round 3
// speedup vs baseline: 1.7471x; 1.0167x over previous
#include <cuda_runtime.h>
#include <cuda_bf16.h>
#include <math.h>
#include <stdint.h>

// Problem constants
#define BB 2
#define SS 1024
#define DD 512
#define VV 32000
#define MM 2048          // BB*SS rows
#define G3 1536          // 3*DD
#define GRU_CTAS 128

// ---------------- scratch (device globals; no runtime allocation) ----------------
__device__ float d_xproj[MM * G3];
__device__ float d_gru[MM * DD];
__device__ float d_h[2][BB * DD];
__device__ unsigned d_bar;
__device__ float d_Q[MM * DD];
__device__ float d_Kc[MM * DD];
__device__ float d_probs[BB * SS * SS];
__device__ float d_ctx[MM * DD];
__device__ __nv_bfloat16 d_comb_bf[MM * 2 * DD];
__device__ __nv_bfloat16 d_genW_bf[(size_t)VV * 2 * DD];
__device__ float d_gate[MM];
__device__ float d_logits[65536000];
__device__ float d_rowmax[MM];
__device__ float d_rowsum[MM];

// =====================================================================
// K1: x_emb gather + x_proj = x_emb @ W_ih^T + b_ih
// =====================================================================
__global__ void k_xproj(const int* __restrict__ x,
                        const float* __restrict__ tok_emb,
                        const float* __restrict__ pos_emb,
                        const float* __restrict__ W_ih,
                        const float* __restrict__ b_ih)
{
    const int m0 = blockIdx.y * 64;
    const int n0 = blockIdx.x * 64;
    __shared__ float As[16][64];
    __shared__ float Bs[16][64];
    __shared__ int tokS[64];
    __shared__ int sS[64];

    const int t = threadIdx.x;
    if (t < 64) {
        int m = m0 + t;
        int b = m & 1, s = m >> 1;
        tokS[t] = x[b * SS + s];
        sS[t] = s;
    }
    __syncthreads();

    const int lrow = t >> 2;
    const int lk4  = (t & 3) * 4;
    const int ty = t >> 4, tx = t & 15;
    float acc[4][4];
#pragma unroll
    for (int i = 0; i < 4; i++)
#pragma unroll
        for (int j = 0; j < 4; j++) acc[i][j] = 0.f;

    for (int k0 = 0; k0 < DD; k0 += 16) {
        float4 te = *(const float4*)&tok_emb[(size_t)tokS[lrow] * DD + k0 + lk4];
        float4 pe = *(const float4*)&pos_emb[(size_t)sS[lrow] * DD + k0 + lk4];
        float4 bv = *(const float4*)&W_ih[(size_t)(n0 + lrow) * DD + k0 + lk4];
        As[lk4 + 0][lrow] = te.x + pe.x;
        As[lk4 + 1][lrow] = te.y + pe.y;
        As[lk4 + 2][lrow] = te.z + pe.z;
        As[lk4 + 3][lrow] = te.w + pe.w;
        Bs[lk4 + 0][lrow] = bv.x;
        Bs[lk4 + 1][lrow] = bv.y;
        Bs[lk4 + 2][lrow] = bv.z;
        Bs[lk4 + 3][lrow] = bv.w;
        __syncthreads();
#pragma unroll
        for (int kk = 0; kk < 16; kk++) {
            float4 av = *(float4*)&As[kk][ty * 4];
            float4 bv2 = *(float4*)&Bs[kk][tx * 4];
            float a[4] = {av.x, av.y, av.z, av.w};
            float b2[4] = {bv2.x, bv2.y, bv2.z, bv2.w};
#pragma unroll
            for (int i = 0; i < 4; i++)
#pragma unroll
                for (int j = 0; j < 4; j++) acc[i][j] += a[i] * b2[j];
        }
        __syncthreads();
    }
#pragma unroll
    for (int i = 0; i < 4; i++) {
        int m = m0 + ty * 4 + i;
#pragma unroll
        for (int j = 0; j < 4; j++) {
            int n = n0 + tx * 4 + j;
            d_xproj[(size_t)m * G3 + n] = acc[i][j] + b_ih[n];
        }
    }
}

// =====================================================================
// K2: init barrier + h0
// =====================================================================
__global__ void k_init()
{
    int t = threadIdx.x;
    for (int i = t; i < 2 * BB * DD; i += blockDim.x) ((float*)d_h)[i] = 0.f;
    if (t == 0) d_bar = 0u;
}

// =====================================================================
// K2b: convert gen_W to bf16
// =====================================================================
__global__ void k_convW(const float* __restrict__ W)
{
    size_t i = ((size_t)blockIdx.x * 256 + threadIdx.x) * 8;
    float4 f0 = *(const float4*)&W[i];
    float4 f1 = *(const float4*)&W[i + 4];
    __nv_bfloat16 h[8];
    h[0] = __float2bfloat16(f0.x); h[1] = __float2bfloat16(f0.y);
    h[2] = __float2bfloat16(f0.z); h[3] = __float2bfloat16(f0.w);
    h[4] = __float2bfloat16(f1.x); h[5] = __float2bfloat16(f1.y);
    h[6] = __float2bfloat16(f1.z); h[7] = __float2bfloat16(f1.w);
    *(uint4*)&d_genW_bf[i] = *(uint4*)h;
}

// =====================================================================
// K3: GRU recurrence. 128 persistent CTAs. release-red barrier.
// =====================================================================
__global__ void k_gru(const float* __restrict__ W_hh,
                      const float* __restrict__ b_hh)
{
    __shared__ float Wsm[4 * 3 * DD];
    __shared__ float h_sm[BB * DD];

    const int t = threadIdx.x;
    const int c = blockIdx.x;
    const int d_base = c * 4;

    for (int i = t; i < 1536; i += 256) {
        int fi = i * 4;
        int dl = fi / 1536;
        int rem = fi - dl * 1536;
        int g = rem / 512;
        int k = rem & 511;
        *(float4*)&Wsm[fi] =
            *(const float4*)&W_hh[(size_t)(g * DD + d_base + dl) * DD + k];
    }

    const int w = t >> 5, lane = t & 31;
    const int b = w & 1, dl = w >> 1;
    const int d = d_base + dl;
    const float bh_r = b_hh[d];
    const float bh_z = b_hh[DD + d];
    const float bh_n = b_hh[2 * DD + d];
    const float* Wr = &Wsm[(dl * 3 + 0) * DD];
    const float* Wz = &Wsm[(dl * 3 + 1) * DD];
    const float* Wn = &Wsm[(dl * 3 + 2) * DD];
    __syncthreads();

    unsigned long long bar_addr;
    asm("cvta.global.u64 %0, %1;" : "=l"(bar_addr) : "l"(&d_bar));

    for (int s = 0; s < SS; ++s) {
        if (s > 0 && t == 0) {
            unsigned target = (unsigned)GRU_CTAS * (unsigned)s;
            unsigned v;
            do {
                asm volatile("ld.acquire.gpu.global.u32 %0, [%1];"
                             : "=r"(v) : "l"(bar_addr));
            } while (v < target);
        }
        __syncthreads();

        float4 hv = __ldcv((const float4*)&d_h[s & 1][0] + t);
        *(float4*)&h_sm[t * 4] = hv;
        __syncthreads();

        float xr = 0.f, xz = 0.f, xn = 0.f;
        if (lane == 0) {
            const float* xp = &d_xproj[(size_t)(s * 2 + b) * G3];
            xr = xp[d]; xz = xp[DD + d]; xn = xp[2 * DD + d];
        }

        const float* hb = &h_sm[b * DD];
        float a0 = 0.f, a1 = 0.f, a2 = 0.f;
#pragma unroll
        for (int k = 0; k < 16; k++) {
            float hv2 = hb[lane * 16 + k];
            a0 = fmaf(hv2, Wr[lane * 16 + k], a0);
            a1 = fmaf(hv2, Wz[lane * 16 + k], a1);
            a2 = fmaf(hv2, Wn[lane * 16 + k], a2);
        }
#pragma unroll
        for (int off = 16; off > 0; off >>= 1) {
            a0 += __shfl_down_sync(0xffffffffu, a0, off);
            a1 += __shfl_down_sync(0xffffffffu, a1, off);
            a2 += __shfl_down_sync(0xffffffffu, a2, off);
        }
        if (lane == 0) {
            float r = 1.f / (1.f + expf(-(xr + a0 + bh_r)));
            float z = 1.f / (1.f + expf(-(xz + a1 + bh_z)));
            float n = tanhf(xn + r * (a2 + bh_n));
            float hold = hb[d];
            float hn = (1.f - z) * n + z * hold;
            d_h[(s + 1) & 1][b * DD + d] = hn;
            d_gru[(size_t)(b * SS + s) * DD + d] = hn;
        }
        __syncthreads();
        if (t == 0)
            asm volatile("red.release.gpu.global.add.u32 [%0], %1;"
                         :: "l"(bar_addr), "r"(1u) : "memory");
    }
}

// =====================================================================
// K4: Q/K projection
// =====================================================================
template <int SEL>
__global__ void k_qk(const float* __restrict__ W)
{
    const int m0 = blockIdx.y * 64;
    const int n0 = blockIdx.x * 64;
    __shared__ float As[16][64];
    __shared__ float Bs[16][64];
    const int t = threadIdx.x;
    const int lrow = t >> 2, lk4 = (t & 3) * 4;
    const int ty = t >> 4, tx = t & 15;
    float acc[4][4];
#pragma unroll
    for (int i = 0; i < 4; i++)
#pragma unroll
        for (int j = 0; j < 4; j++) acc[i][j] = 0.f;

    for (int k0 = 0; k0 < DD; k0 += 16) {
        float4 a = *(const float4*)&d_gru[(size_t)(m0 + lrow) * DD + k0 + lk4];
        float4 bv = *(const float4*)&W[(size_t)(n0 + lrow) * DD + k0 + lk4];
        As[lk4 + 0][lrow] = a.x; As[lk4 + 1][lrow] = a.y;
        As[lk4 + 2][lrow] = a.z; As[lk4 + 3][lrow] = a.w;
        Bs[lk4 + 0][lrow] = bv.x; Bs[lk4 + 1][lrow] = bv.y;
        Bs[lk4 + 2][lrow] = bv.z; Bs[lk4 + 3][lrow] = bv.w;
        __syncthreads();
#pragma unroll
        for (int kk = 0; kk < 16; kk++) {
            float4 av = *(float4*)&As[kk][ty * 4];
            float4 bv2 = *(float4*)&Bs[kk][tx * 4];
            float a2[4] = {av.x, av.y, av.z, av.w};
            float b2[4] = {bv2.x, bv2.y, bv2.z, bv2.w};
#pragma unroll
            for (int i = 0; i < 4; i++)
#pragma unroll
                for (int j = 0; j < 4; j++) acc[i][j] += a2[i] * b2[j];
        }
        __syncthreads();
    }
    float* C = SEL ? d_Kc : d_Q;
#pragma unroll
    for (int i = 0; i < 4; i++)
#pragma unroll
        for (int j = 0; j < 4; j++)
            C[(size_t)(m0 + ty * 4 + i) * DD + n0 + tx * 4 + j] = acc[i][j];
}

// =====================================================================
// K5: RoPE in place on Q and K
// =====================================================================
__global__ void k_rope()
{
    int m = blockIdx.x;
    int i = threadIdx.x;
    int s = m & (SS - 1);
    float invf = powf(10000.f, -((float)(2 * i) / (float)DD));
    float ang = (float)s * invf;
    float sn, cs;
    sincosf(ang, &sn, &cs);
    size_t base = (size_t)m * DD + 2 * i;
    float q0 = d_Q[base], q1 = d_Q[base + 1];
    d_Q[base]     = q0 * cs - q1 * sn;
    d_Q[base + 1] = q1 * cs + q0 * sn;
    float k0 = d_Kc[base], k1 = d_Kc[base + 1];
    d_Kc[base]     = k0 * cs - k1 * sn;
    d_Kc[base + 1] = k1 * cs + k0 * sn;
}

// =====================================================================
// K6: scores = Q K^T / sqrt(D) with causal mask
// =====================================================================
__global__ void k_scores()
{
    const int z = blockIdx.z;
    const int m0 = blockIdx.y * 64;
    const int n0 = blockIdx.x * 64;
    const int t = threadIdx.x;
    float* C = d_probs + (size_t)z * SS * SS;

    if (n0 >= m0 + 64) {
        for (int e = t; e < 64 * 64; e += 256) {
            int i = e >> 6, j = e & 63;
            C[(size_t)(m0 + i) * SS + n0 + j] = -1e30f;
        }
        return;
    }

    const float* A = d_Q + (size_t)z * SS * DD;
    const float* Bm = d_Kc + (size_t)z * SS * DD;
    __shared__ float As[16][64];
    __shared__ float Bs[16][64];
    const int lrow = t >> 2, lk4 = (t & 3) * 4;
    const int ty = t >> 4, tx = t & 15;
    float acc[4][4];
#pragma unroll
    for (int i = 0; i < 4; i++)
#pragma unroll
        for (int j = 0; j < 4; j++) acc[i][j] = 0.f;

    for (int k0 = 0; k0 < DD; k0 += 16) {
        float4 a = *(const float4*)&A[(size_t)(m0 + lrow) * DD + k0 + lk4];
        float4 bv = *(const float4*)&Bm[(size_t)(n0 + lrow) * DD + k0 + lk4];
        As[lk4 + 0][lrow] = a.x; As[lk4 + 1][lrow] = a.y;
        As[lk4 + 2][lrow] = a.z; As[lk4 + 3][lrow] = a.w;
        Bs[lk4 + 0][lrow] = bv.x; Bs[lk4 + 1][lrow] = bv.y;
        Bs[lk4 + 2][lrow] = bv.z; Bs[lk4 + 3][lrow] = bv.w;
        __syncthreads();
#pragma unroll
        for (int kk = 0; kk < 16; kk++) {
            float4 av = *(float4*)&As[kk][ty * 4];
            float4 bv2 = *(float4*)&Bs[kk][tx * 4];
            float a2[4] = {av.x, av.y, av.z, av.w};
            float b2[4] = {bv2.x, bv2.y, bv2.z, bv2.w};
#pragma unroll
            for (int i = 0; i < 4; i++)
#pragma unroll
                for (int j = 0; j < 4; j++) acc[i][j] += a2[i] * b2[j];
        }
        __syncthreads();
    }
    const float scale = 0.04419417382415922f;
#pragma unroll
    for (int i = 0; i < 4; i++) {
        int gi = m0 + ty * 4 + i;
#pragma unroll
        for (int j = 0; j < 4; j++) {
            int gj = n0 + tx * 4 + j;
            float v = acc[i][j] * scale;
            if (gj > gi) v = -1e30f;
            C[(size_t)gi * SS + gj] = v;
        }
    }
}

// =====================================================================
// K7: row softmax over 1024
// =====================================================================
__global__ void k_softmax_rows()
{
    int m = blockIdx.x;
    float* row = d_probs + (size_t)m * SS;
    const int t = threadIdx.x;
    __shared__ float red[256];

    float4 lv = *(float4*)&row[t * 4];
    float mx = fmaxf(fmaxf(lv.x, lv.y), fmaxf(lv.z, lv.w));
    red[t] = mx;
    __syncthreads();
    for (int off = 128; off > 0; off >>= 1) {
        if (t < off) red[t] = fmaxf(red[t], red[t + off]);
        __syncthreads();
    }
    mx = red[0];
    __syncthreads();

    float4 e;
    e.x = expf(lv.x - mx); e.y = expf(lv.y - mx);
    e.z = expf(lv.z - mx); e.w = expf(lv.w - mx);
    red[t] = e.x + e.y + e.z + e.w;
    __syncthreads();
    for (int off = 128; off > 0; off >>= 1) {
        if (t < off) red[t] += red[t + off];
        __syncthreads();
    }
    float inv = 1.f / red[0];
    e.x *= inv; e.y *= inv; e.z *= inv; e.w *= inv;
    *(float4*)&row[t * 4] = e;
}

// =====================================================================
// K8: context = probs @ gru
// =====================================================================
__global__ void k_ctx()
{
    const int z = blockIdx.z;
    const int m0 = blockIdx.y * 64;
    const int n0 = blockIdx.x * 64;
    const float* A = d_probs + (size_t)z * SS * SS;
    const float* Bm = d_gru + (size_t)z * SS * DD;
    float* C = d_ctx + (size_t)z * SS * DD;

    __shared__ float As[16][64];
    __shared__ float Bs[16][64];
    const int t = threadIdx.x;
    const int lrow = t >> 2, lk4 = (t & 3) * 4;
    const int bk = t >> 4, bn4 = (t & 15) * 4;
    const int ty = t >> 4, tx = t & 15;
    float acc[4][4];
#pragma unroll
    for (int i = 0; i < 4; i++)
#pragma unroll
        for (int j = 0; j < 4; j++) acc[i][j] = 0.f;

    for (int k0 = 0; k0 < SS; k0 += 16) {
        float4 a = *(const float4*)&A[(size_t)(m0 + lrow) * SS + k0 + lk4];
        As[lk4 + 0][lrow] = a.x; As[lk4 + 1][lrow] = a.y;
        As[lk4 + 2][lrow] = a.z; As[lk4 + 3][lrow] = a.w;
        float4 bv = *(const float4*)&Bm[(size_t)(k0 + bk) * DD + n0 + bn4];
        *(float4*)&Bs[bk][bn4] = bv;
        __syncthreads();
#pragma unroll
        for (int kk = 0; kk < 16; kk++) {
            float4 av = *(float4*)&As[kk][ty * 4];
            float4 bv2 = *(float4*)&Bs[kk][tx * 4];
            float a2[4] = {av.x, av.y, av.z, av.w};
            float b2[4] = {bv2.x, bv2.y, bv2.z, bv2.w};
#pragma unroll
            for (int i = 0; i < 4; i++)
#pragma unroll
                for (int j = 0; j < 4; j++) acc[i][j] += a2[i] * b2[j];
        }
        __syncthreads();
    }
#pragma unroll
    for (int i = 0; i < 4; i++)
#pragma unroll
        for (int j = 0; j < 4; j++)
            C[(size_t)(m0 + ty * 4 + i) * DD + n0 + tx * 4 + j] = acc[i][j];
}

// =====================================================================
// K9: combined (bf16) = [gru, ctx]; gate
// =====================================================================
__global__ void k_comb_gate(const float* __restrict__ gate_W,
                            const float* __restrict__ gate_b)
{
    int m = blockIdx.x;
    int t = threadIdx.x;
    __shared__ float red[256];
    float acc = 0.f;
    for (int idx = t; idx < DD; idx += 256) {
        float g = d_gru[(size_t)m * DD + idx];
        float c = d_ctx[(size_t)m * DD + idx];
        d_comb_bf[(size_t)m * 2 * DD + idx] = __float2bfloat16(g);
        d_comb_bf[(size_t)m * 2 * DD + DD + idx] = __float2bfloat16(c);
        acc += g * gate_W[idx] + c * gate_W[DD + idx];
    }
    red[t] = acc;
    __syncthreads();
    for (int off = 128; off > 0; off >>= 1) {
        if (t < off) red[t] += red[t + off];
        __syncthreads();
    }
    if (t == 0) d_gate[m] = 1.f / (1.f + expf(-(red[0] + gate_b[0])));
}

// =====================================================================
// K10: gen logits GEMM via mma.sync bf16, cp.async double-buffered.
// grid = (M/128, N/128)  [m-fast so gen_W tiles hit L2]
// =====================================================================
__device__ __forceinline__ void mma_bf16(float& c0, float& c1, float& c2, float& c3,
                                         uint32_t a0, uint32_t a1, uint32_t a2, uint32_t a3,
                                         uint32_t b0, uint32_t b1)
{
    asm volatile(
        "mma.sync.aligned.m16n8k16.row.col.f32.bf16.bf16.f32 "
        "{%0,%1,%2,%3}, {%4,%5,%6,%7}, {%8,%9}, {%0,%1,%2,%3};\n"
        : "+f"(c0), "+f"(c1), "+f"(c2), "+f"(c3)
        : "r"(a0), "r"(a1), "r"(a2), "r"(a3), "r"(b0), "r"(b1));
}

__device__ __forceinline__ void cp16(void* smem, const void* gmem)
{
    uint32_t sa = (uint32_t)__cvta_generic_to_shared(smem);
    asm volatile("cp.async.cg.shared.global [%0], [%1], 16;\n"
                 :: "r"(sa), "l"(gmem));
}

#define KC 32
__global__ void __launch_bounds__(256) k_gen_mma(const float* __restrict__ bias)
{
    const int m0 = blockIdx.x * 128;
    const int n0 = blockIdx.y * 128;
    __shared__ __nv_bfloat16 As[2][128][40];   // 20KB (2 stages)
    __shared__ __nv_bfloat16 Bs[2][128][40];   // 20KB

    const int t = threadIdx.x;
    const int w = t >> 5, lane = t & 31;
    const int wm = (w >> 2) * 64;
    const int wn = (w & 3) * 32;
    const int g = lane >> 2, q = lane & 3;

    // loader mapping: 2 chunks of 8 bf16 per thread per tile
    const int lr0 = t >> 1;                 // rows via c = it*256+t : row=c>>2
    (void)lr0;

    float acc[4][4][4];
#pragma unroll
    for (int i = 0; i < 4; i++)
#pragma unroll
        for (int j = 0; j < 4; j++)
#pragma unroll
            for (int r = 0; r < 4; r++) acc[i][j][r] = 0.f;

    // stage chunk k0 into buffer buf
    auto stage = [&](int buf, int k0) {
#pragma unroll
        for (int it = 0; it < 2; it++) {
            int c = it * 256 + t;
            int row = c >> 2;
            int c8 = (c & 3) * 8;
            cp16(&As[buf][row][c8],
                 &d_comb_bf[(size_t)(m0 + row) * (2 * DD) + k0 + c8]);
            cp16(&Bs[buf][row][c8],
                 &d_genW_bf[(size_t)(n0 + row) * (2 * DD) + k0 + c8]);
        }
    };

    stage(0, 0);
    asm volatile("cp.async.commit_group;\n" ::);

    for (int k0 = 0; k0 < 2 * DD; k0 += KC) {
        int buf = (k0 / KC) & 1;
        if (k0 + KC < 2 * DD) {
            stage(buf ^ 1, k0 + KC);
            asm volatile("cp.async.commit_group;\n" ::);
            asm volatile("cp.async.wait_group 1;\n" ::);
        } else {
            asm volatile("cp.async.wait_group 0;\n" ::);
        }
        __syncthreads();

#pragma unroll
        for (int kk = 0; kk < KC; kk += 16) {
            uint32_t af[4][4];
#pragma unroll
            for (int i = 0; i < 4; i++) {
                int r = wm + i * 16 + g;
                af[i][0] = *(const uint32_t*)&As[buf][r][kk + q * 2];
                af[i][1] = *(const uint32_t*)&As[buf][r + 8][kk + q * 2];
                af[i][2] = *(const uint32_t*)&As[buf][r][kk + q * 2 + 8];
                af[i][3] = *(const uint32_t*)&As[buf][r + 8][kk + q * 2 + 8];
            }
            uint32_t bfr[4][2];
#pragma unroll
            for (int j = 0; j < 4; j++) {
                int n = wn + j * 8 + g;
                bfr[j][0] = *(const uint32_t*)&Bs[buf][n][kk + q * 2];
                bfr[j][1] = *(const uint32_t*)&Bs[buf][n][kk + q * 2 + 8];
            }
#pragma unroll
            for (int i = 0; i < 4; i++)
#pragma unroll
                for (int j = 0; j < 4; j++)
                    mma_bf16(acc[i][j][0], acc[i][j][1], acc[i][j][2], acc[i][j][3],
                             af[i][0], af[i][1], af[i][2], af[i][3],
                             bfr[j][0], bfr[j][1]);
        }
        __syncthreads();
    }

#pragma unroll
    for (int j = 0; j < 4; j++) {
        int n = n0 + wn + j * 8 + q * 2;
        float2 bv = *(const float2*)&bias[n];
#pragma unroll
        for (int i = 0; i < 4; i++) {
            size_t r0 = (size_t)(m0 + wm + i * 16 + g);
            size_t r1 = r0 + 8;
            float2 o0 = {acc[i][j][0] + bv.x, acc[i][j][1] + bv.y};
            float2 o1 = {acc[i][j][2] + bv.x, acc[i][j][3] + bv.y};
            *(float2*)&d_logits[r0 * VV + n] = o0;
            *(float2*)&d_logits[r1 * VV + n] = o1;
        }
    }
}

// =====================================================================
// K11: fused row softmax over V + gate blend -> out
// =====================================================================
__global__ void k_softmaxV(float* __restrict__ out)
{
    int m = blockIdx.x;
    const float* row = d_logits + (size_t)m * VV;
    const int t = threadIdx.x;
    float mx = -1e30f, sm = 0.f;
    for (int v4 = t; v4 < VV / 4; v4 += 256) {
        float4 l = *(const float4*)&row[v4 * 4];
        float vals[4] = {l.x, l.y, l.z, l.w};
#pragma unroll
        for (int u = 0; u < 4; u++) {
            float l1 = vals[u];
            if (l1 > mx) { sm = sm * __expf(mx - l1) + 1.f; mx = l1; }
            else sm += __expf(l1 - mx);
        }
    }
    __shared__ float smx[256], ssm[256];
    smx[t] = mx; ssm[t] = sm;
    for (int off = 128; off > 0; off >>= 1) {
        __syncthreads();
        if (t < off) {
            float m2 = smx[t + off], s2 = ssm[t + off];
            if (m2 > mx) { sm = sm * __expf(mx - m2) + s2; mx = m2; }
            else sm += s2 * __expf(m2 - mx);
            smx[t] = mx; ssm[t] = sm;
        }
    }
    __syncthreads();
    mx = smx[0];
    float g = d_gate[m];
    float is = g / ssm[0];
    float* orow = out + (size_t)m * VV;
    for (int v4 = t; v4 < VV / 4; v4 += 256) {
        float4 l = *(const float4*)&row[v4 * 4];
        float4 o;
        o.x = __expf(l.x - mx) * is;
        o.y = __expf(l.y - mx) * is;
        o.z = __expf(l.z - mx) * is;
        o.w = __expf(l.w - mx) * is;
        *(float4*)&orow[v4 * 4] = o;
    }
}

// =====================================================================
// K13: scatter copy-probs
// =====================================================================
__global__ void k_scatter(const int* __restrict__ x, float* __restrict__ out)
{
    int m = blockIdx.x;
    int b = m >> 10;
    int i = m & (SS - 1);
    float om = 1.f - d_gate[m];
    const float* pr = d_probs + (size_t)m * SS;
    float* orow = out + (size_t)m * VV;
    for (int j = threadIdx.x; j <= i; j += 256) {
        atomicAdd(&orow[x[b * SS + j]], om * pr[j]);
    }
}

// =====================================================================
// launch
// =====================================================================
extern "C" void kernel_launch(void* const* d_in, const int* in_sizes, int n_in,
                              void* d_out, int out_size)
{
    const int*   x        = (const int*)d_in[0];
    const float* tok_emb  = (const float*)d_in[1];
    const float* pos_emb  = (const float*)d_in[2];
    const float* W_ih     = (const float*)d_in[3];
    const float* W_hh     = (const float*)d_in[4];
    const float* b_ih     = (const float*)d_in[5];
    const float* b_hh     = (const float*)d_in[6];
    const float* W_q      = (const float*)d_in[7];
    const float* W_k      = (const float*)d_in[8];
    const float* gen_W    = (const float*)d_in[9];
    const float* gen_b    = (const float*)d_in[10];
    const float* gate_W   = (const float*)d_in[11];
    const float* gate_b   = (const float*)d_in[12];
    float* out = (float*)d_out;

    k_xproj<<<dim3(G3 / 64, MM / 64), 256>>>(x, tok_emb, pos_emb, W_ih, b_ih);
    k_init<<<1, 256>>>();
    k_convW<<<(VV * 2 * DD) / (8 * 256), 256>>>(gen_W);
    k_gru<<<GRU_CTAS, 256>>>(W_hh, b_hh);
    k_qk<0><<<dim3(DD / 64, MM / 64), 256>>>(W_q);
    k_qk<1><<<dim3(DD / 64, MM / 64), 256>>>(W_k);
    k_rope<<<MM, 256>>>();
    k_scores<<<dim3(SS / 64, SS / 64, BB), 256>>>();
    k_softmax_rows<<<MM, 256>>>();
    k_ctx<<<dim3(DD / 64, SS / 64, BB), 256>>>();
    k_comb_gate<<<MM, 256>>>(gate_W, gate_b);
    k_gen_mma<<<dim3(MM / 128, VV / 128), 256>>>(gen_b);
    k_softmaxV<<<MM, 256>>>(out);
    k_scatter<<<MM, 256>>>(x, out);
}

// round 5
// speedup vs baseline: 1.8304x; 1.0477x over previous
#include <cuda_runtime.h>
#include <cuda_bf16.h>
#include <math.h>
#include <stdint.h>

// Problem constants
#define BB 2
#define SS 1024
#define DD 512
#define VV 32000
#define MM 2048
#define G3 1536
#define GRU_CTAS 128

// ---------------- scratch ----------------
__device__ float d_xproj[MM * G3];
__device__ float d_gru[MM * DD];
__device__ float d_h[2][BB * DD];
__device__ unsigned d_bar;
__device__ float d_Q[MM * DD];
__device__ float d_Kc[MM * DD];
__device__ float d_probs[BB * SS * SS];
__device__ float d_ctx[MM * DD];
__device__ __nv_bfloat16 d_comb_bf[MM * 2 * DD];
__device__ __nv_bfloat16 d_genW_bf[(size_t)VV * 2 * DD];
__device__ float d_gate[MM];
__device__ float d_logits[65536000];

// =====================================================================
// K1: x_emb gather + x_proj
// =====================================================================
__global__ void k_xproj(const int* __restrict__ x,
                        const float* __restrict__ tok_emb,
                        const float* __restrict__ pos_emb,
                        const float* __restrict__ W_ih,
                        const float* __restrict__ b_ih)
{
    const int m0 = blockIdx.y * 64;
    const int n0 = blockIdx.x * 64;
    __shared__ float As[16][64];
    __shared__ float Bs[16][64];
    __shared__ int tokS[64];
    __shared__ int sS[64];

    const int t = threadIdx.x;
    if (t < 64) {
        int m = m0 + t;
        int b = m & 1, s = m >> 1;
        tokS[t] = x[b * SS + s];
        sS[t] = s;
    }
    __syncthreads();

    const int lrow = t >> 2;
    const int lk4  = (t & 3) * 4;
    const int ty = t >> 4, tx = t & 15;
    float acc[4][4];
#pragma unroll
    for (int i = 0; i < 4; i++)
#pragma unroll
        for (int j = 0; j < 4; j++) acc[i][j] = 0.f;

    for (int k0 = 0; k0 < DD; k0 += 16) {
        float4 te = *(const float4*)&tok_emb[(size_t)tokS[lrow] * DD + k0 + lk4];
        float4 pe = *(const float4*)&pos_emb[(size_t)sS[lrow] * DD + k0 + lk4];
        float4 bv = *(const float4*)&W_ih[(size_t)(n0 + lrow) * DD + k0 + lk4];
        As[lk4 + 0][lrow] = te.x + pe.x;
        As[lk4 + 1][lrow] = te.y + pe.y;
        As[lk4 + 2][lrow] = te.z + pe.z;
        As[lk4 + 3][lrow] = te.w + pe.w;
        Bs[lk4 + 0][lrow] = bv.x;
        Bs[lk4 + 1][lrow] = bv.y;
        Bs[lk4 + 2][lrow] = bv.z;
        Bs[lk4 + 3][lrow] = bv.w;
        __syncthreads();
#pragma unroll
        for (int kk = 0; kk < 16; kk++) {
            float4 av = *(float4*)&As[kk][ty * 4];
            float4 bv2 = *(float4*)&Bs[kk][tx * 4];
            float a[4] = {av.x, av.y, av.z, av.w};
            float b2[4] = {bv2.x, bv2.y, bv2.z, bv2.w};
#pragma unroll
            for (int i = 0; i < 4; i++)
#pragma unroll
                for (int j = 0; j < 4; j++) acc[i][j] += a[i] * b2[j];
        }
        __syncthreads();
    }
#pragma unroll
    for (int i = 0; i < 4; i++) {
        int m = m0 + ty * 4 + i;
#pragma unroll
        for (int j = 0; j < 4; j++) {
            int n = n0 + tx * 4 + j;
            d_xproj[(size_t)m * G3 + n] = acc[i][j] + b_ih[n];
        }
    }
}

// =====================================================================
// K2: init barrier + h0
// =====================================================================
__global__ void k_init()
{
    int t = threadIdx.x;
    for (int i = t; i < 2 * BB * DD; i += blockDim.x) ((float*)d_h)[i] = 0.f;
    if (t == 0) d_bar = 0u;
}

// =====================================================================
// K2b: convert gen_W to bf16
// =====================================================================
__global__ void k_convW(const float* __restrict__ W)
{
    size_t i = ((size_t)blockIdx.x * 256 + threadIdx.x) * 8;
    float4 f0 = *(const float4*)&W[i];
    float4 f1 = *(const float4*)&W[i + 4];
    __nv_bfloat16 h[8];
    h[0] = __float2bfloat16(f0.x); h[1] = __float2bfloat16(f0.y);
    h[2] = __float2bfloat16(f0.z); h[3] = __float2bfloat16(f0.w);
    h[4] = __float2bfloat16(f1.x); h[5] = __float2bfloat16(f1.y);
    h[6] = __float2bfloat16(f1.z); h[7] = __float2bfloat16(f1.w);
    *(uint4*)&d_genW_bf[i] = *(uint4*)h;
}

// =====================================================================
// K3: GRU recurrence (persistent, gpu-scope release/acquire barrier)
// =====================================================================
__global__ void k_gru(const float* __restrict__ W_hh,
                      const float* __restrict__ b_hh)
{
    __shared__ float Wsm[4 * 3 * DD];
    __shared__ float h_sm[BB * DD];

    const int t = threadIdx.x;
    const int c = blockIdx.x;
    const int d_base = c * 4;

    for (int i = t; i < 1536; i += 256) {
        int fi = i * 4;
        int dl = fi / 1536;
        int rem = fi - dl * 1536;
        int g = rem / 512;
        int k = rem & 511;
        *(float4*)&Wsm[fi] =
            *(const float4*)&W_hh[(size_t)(g * DD + d_base + dl) * DD + k];
    }

    const int w = t >> 5, lane = t & 31;
    const int b = w & 1, dl = w >> 1;
    const int d = d_base + dl;
    const float bh_r = b_hh[d];
    const float bh_z = b_hh[DD + d];
    const float bh_n = b_hh[2 * DD + d];
    const float* Wr = &Wsm[(dl * 3 + 0) * DD];
    const float* Wz = &Wsm[(dl * 3 + 1) * DD];
    const float* Wn = &Wsm[(dl * 3 + 2) * DD];
    __syncthreads();

    unsigned long long bar_addr;
    asm("cvta.global.u64 %0, %1;" : "=l"(bar_addr) : "l"(&d_bar));

    for (int s = 0; s < SS; ++s) {
        if (s > 0 && t == 0) {
            unsigned target = (unsigned)GRU_CTAS * (unsigned)s;
            unsigned v;
            do {
                asm volatile("ld.acquire.gpu.global.u32 %0, [%1];"
                             : "=r"(v) : "l"(bar_addr));
            } while (v < target);
        }
        __syncthreads();

        float4 hv = __ldcv((const float4*)&d_h[s & 1][0] + t);
        *(float4*)&h_sm[t * 4] = hv;
        __syncthreads();

        float xr = 0.f, xz = 0.f, xn = 0.f;
        if (lane == 0) {
            const float* xp = &d_xproj[(size_t)(s * 2 + b) * G3];
            xr = xp[d]; xz = xp[DD + d]; xn = xp[2 * DD + d];
        }

        const float* hb = &h_sm[b * DD];
        float a0 = 0.f, a1 = 0.f, a2 = 0.f;
#pragma unroll
        for (int k = 0; k < 16; k++) {
            float hv2 = hb[lane * 16 + k];
            a0 = fmaf(hv2, Wr[lane * 16 + k], a0);
            a1 = fmaf(hv2, Wz[lane * 16 + k], a1);
            a2 = fmaf(hv2, Wn[lane * 16 + k], a2);
        }
#pragma unroll
        for (int off = 16; off > 0; off >>= 1) {
            a0 += __shfl_down_sync(0xffffffffu, a0, off);
            a1 += __shfl_down_sync(0xffffffffu, a1, off);
            a2 += __shfl_down_sync(0xffffffffu, a2, off);
        }
        if (lane == 0) {
            float r = 1.f / (1.f + expf(-(xr + a0 + bh_r)));
            float z = 1.f / (1.f + expf(-(xz + a1 + bh_z)));
            float n = tanhf(xn + r * (a2 + bh_n));
            float hold = hb[d];
            float hn = (1.f - z) * n + z * hold;
            d_h[(s + 1) & 1][b * DD + d] = hn;
            d_gru[(size_t)(b * SS + s) * DD + d] = hn;
        }
        __syncthreads();
        if (t == 0)
            asm volatile("red.release.gpu.global.add.u32 [%0], %1;"
                         :: "l"(bar_addr), "r"(1u) : "memory");
    }
}

// =====================================================================
// K4: Q/K projection
// =====================================================================
template <int SEL>
__global__ void k_qk(const float* __restrict__ W)
{
    const int m0 = blockIdx.y * 64;
    const int n0 = blockIdx.x * 64;
    __shared__ float As[16][64];
    __shared__ float Bs[16][64];
    const int t = threadIdx.x;
    const int lrow = t >> 2, lk4 = (t & 3) * 4;
    const int ty = t >> 4, tx = t & 15;
    float acc[4][4];
#pragma unroll
    for (int i = 0; i < 4; i++)
#pragma unroll
        for (int j = 0; j < 4; j++) acc[i][j] = 0.f;

    for (int k0 = 0; k0 < DD; k0 += 16) {
        float4 a = *(const float4*)&d_gru[(size_t)(m0 + lrow) * DD + k0 + lk4];
        float4 bv = *(const float4*)&W[(size_t)(n0 + lrow) * DD + k0 + lk4];
        As[lk4 + 0][lrow] = a.x; As[lk4 + 1][lrow] = a.y;
        As[lk4 + 2][lrow] = a.z; As[lk4 + 3][lrow] = a.w;
        Bs[lk4 + 0][lrow] = bv.x; Bs[lk4 + 1][lrow] = bv.y;
        Bs[lk4 + 2][lrow] = bv.z; Bs[lk4 + 3][lrow] = bv.w;
        __syncthreads();
#pragma unroll
        for (int kk = 0; kk < 16; kk++) {
            float4 av = *(float4*)&As[kk][ty * 4];
            float4 bv2 = *(float4*)&Bs[kk][tx * 4];
            float a2[4] = {av.x, av.y, av.z, av.w};
            float b2[4] = {bv2.x, bv2.y, bv2.z, bv2.w};
#pragma unroll
            for (int i = 0; i < 4; i++)
#pragma unroll
                for (int j = 0; j < 4; j++) acc[i][j] += a2[i] * b2[j];
        }
        __syncthreads();
    }
    float* C = SEL ? d_Kc : d_Q;
#pragma unroll
    for (int i = 0; i < 4; i++)
#pragma unroll
        for (int j = 0; j < 4; j++)
            C[(size_t)(m0 + ty * 4 + i) * DD + n0 + tx * 4 + j] = acc[i][j];
}

// =====================================================================
// K5: RoPE
// =====================================================================
__global__ void k_rope()
{
    int m = blockIdx.x;
    int i = threadIdx.x;
    int s = m & (SS - 1);
    float invf = powf(10000.f, -((float)(2 * i) / (float)DD));
    float ang = (float)s * invf;
    float sn, cs;
    sincosf(ang, &sn, &cs);
    size_t base = (size_t)m * DD + 2 * i;
    float q0 = d_Q[base], q1 = d_Q[base + 1];
    d_Q[base]     = q0 * cs - q1 * sn;
    d_Q[base + 1] = q1 * cs + q0 * sn;
    float k0 = d_Kc[base], k1 = d_Kc[base + 1];
    d_Kc[base]     = k0 * cs - k1 * sn;
    d_Kc[base + 1] = k1 * cs + k0 * sn;
}

// =====================================================================
// K6: scores
// =====================================================================
__global__ void k_scores()
{
    const int z = blockIdx.z;
    const int m0 = blockIdx.y * 64;
    const int n0 = blockIdx.x * 64;
    const int t = threadIdx.x;
    float* C = d_probs + (size_t)z * SS * SS;

    if (n0 >= m0 + 64) {
        for (int e = t; e < 64 * 64; e += 256) {
            int i = e >> 6, j = e & 63;
            C[(size_t)(m0 + i) * SS + n0 + j] = -1e30f;
        }
        return;
    }

    const float* A = d_Q + (size_t)z * SS * DD;
    const float* Bm = d_Kc + (size_t)z * SS * DD;
    __shared__ float As[16][64];
    __shared__ float Bs[16][64];
    const int lrow = t >> 2, lk4 = (t & 3) * 4;
    const int ty = t >> 4, tx = t & 15;
    float acc[4][4];
#pragma unroll
    for (int i = 0; i < 4; i++)
#pragma unroll
        for (int j = 0; j < 4; j++) acc[i][j] = 0.f;

    for (int k0 = 0; k0 < DD; k0 += 16) {
        float4 a = *(const float4*)&A[(size_t)(m0 + lrow) * DD + k0 + lk4];
        float4 bv = *(const float4*)&Bm[(size_t)(n0 + lrow) * DD + k0 + lk4];
        As[lk4 + 0][lrow] = a.x; As[lk4 + 1][lrow] = a.y;
        As[lk4 + 2][lrow] = a.z; As[lk4 + 3][lrow] = a.w;
        Bs[lk4 + 0][lrow] = bv.x; Bs[lk4 + 1][lrow] = bv.y;
        Bs[lk4 + 2][lrow] = bv.z; Bs[lk4 + 3][lrow] = bv.w;
        __syncthreads();
#pragma unroll
        for (int kk = 0; kk < 16; kk++) {
            float4 av = *(float4*)&As[kk][ty * 4];
            float4 bv2 = *(float4*)&Bs[kk][tx * 4];
            float a2[4] = {av.x, av.y, av.z, av.w};
            float b2[4] = {bv2.x, bv2.y, bv2.z, bv2.w};
#pragma unroll
            for (int i = 0; i < 4; i++)
#pragma unroll
                for (int j = 0; j < 4; j++) acc[i][j] += a2[i] * b2[j];
        }
        __syncthreads();
    }
    const float scale = 0.04419417382415922f;
#pragma unroll
    for (int i = 0; i < 4; i++) {
        int gi = m0 + ty * 4 + i;
#pragma unroll
        for (int j = 0; j < 4; j++) {
            int gj = n0 + tx * 4 + j;
            float v = acc[i][j] * scale;
            if (gj > gi) v = -1e30f;
            C[(size_t)gi * SS + gj] = v;
        }
    }
}

// =====================================================================
// K7: row softmax over 1024
// =====================================================================
__global__ void k_softmax_rows()
{
    int m = blockIdx.x;
    float* row = d_probs + (size_t)m * SS;
    const int t = threadIdx.x;
    __shared__ float red[256];

    float4 lv = *(float4*)&row[t * 4];
    float mx = fmaxf(fmaxf(lv.x, lv.y), fmaxf(lv.z, lv.w));
    red[t] = mx;
    __syncthreads();
    for (int off = 128; off > 0; off >>= 1) {
        if (t < off) red[t] = fmaxf(red[t], red[t + off]);
        __syncthreads();
    }
    mx = red[0];
    __syncthreads();

    float4 e;
    e.x = expf(lv.x - mx); e.y = expf(lv.y - mx);
    e.z = expf(lv.z - mx); e.w = expf(lv.w - mx);
    red[t] = e.x + e.y + e.z + e.w;
    __syncthreads();
    for (int off = 128; off > 0; off >>= 1) {
        if (t < off) red[t] += red[t + off];
        __syncthreads();
    }
    float inv = 1.f / red[0];
    e.x *= inv; e.y *= inv; e.z *= inv; e.w *= inv;
    *(float4*)&row[t * 4] = e;
}

// =====================================================================
// K8: context = probs @ gru
// =====================================================================
__global__ void k_ctx()
{
    const int z = blockIdx.z;
    const int m0 = blockIdx.y * 64;
    const int n0 = blockIdx.x * 64;
    const float* A = d_probs + (size_t)z * SS * SS;
    const float* Bm = d_gru + (size_t)z * SS * DD;
    float* C = d_ctx + (size_t)z * SS * DD;

    __shared__ float As[16][64];
    __shared__ float Bs[16][64];
    const int t = threadIdx.x;
    const int lrow = t >> 2, lk4 = (t & 3) * 4;
    const int bk = t >> 4, bn4 = (t & 15) * 4;
    const int ty = t >> 4, tx = t & 15;
    float acc[4][4];
#pragma unroll
    for (int i = 0; i < 4; i++)
#pragma unroll
        for (int j = 0; j < 4; j++) acc[i][j] = 0.f;

    for (int k0 = 0; k0 < SS; k0 += 16) {
        float4 a = *(const float4*)&A[(size_t)(m0 + lrow) * SS + k0 + lk4];
        As[lk4 + 0][lrow] = a.x; As[lk4 + 1][lrow] = a.y;
        As[lk4 + 2][lrow] = a.z; As[lk4 + 3][lrow] = a.w;
        float4 bv = *(const float4*)&Bm[(size_t)(k0 + bk) * DD + n0 + bn4];
        *(float4*)&Bs[bk][bn4] = bv;
        __syncthreads();
#pragma unroll
        for (int kk = 0; kk < 16; kk++) {
            float4 av = *(float4*)&As[kk][ty * 4];
            float4 bv2 = *(float4*)&Bs[kk][tx * 4];
            float a2[4] = {av.x, av.y, av.z, av.w};
            float b2[4] = {bv2.x, bv2.y, bv2.z, bv2.w};
#pragma unroll
            for (int i = 0; i < 4; i++)
#pragma unroll
                for (int j = 0; j < 4; j++) acc[i][j] += a2[i] * b2[j];
        }
        __syncthreads();
    }
#pragma unroll
    for (int i = 0; i < 4; i++)
#pragma unroll
        for (int j = 0; j < 4; j++)
            C[(size_t)(m0 + ty * 4 + i) * DD + n0 + tx * 4 + j] = acc[i][j];
}

// =====================================================================
// K9: combined (bf16) + gate
// =====================================================================
__global__ void k_comb_gate(const float* __restrict__ gate_W,
                            const float* __restrict__ gate_b)
{
    int m = blockIdx.x;
    int t = threadIdx.x;
    __shared__ float red[256];
    float acc = 0.f;
    for (int idx = t; idx < DD; idx += 256) {
        float g = d_gru[(size_t)m * DD + idx];
        float c = d_ctx[(size_t)m * DD + idx];
        d_comb_bf[(size_t)m * 2 * DD + idx] = __float2bfloat16(g);
        d_comb_bf[(size_t)m * 2 * DD + DD + idx] = __float2bfloat16(c);
        acc += g * gate_W[idx] + c * gate_W[DD + idx];
    }
    red[t] = acc;
    __syncthreads();
    for (int off = 128; off > 0; off >>= 1) {
        if (t < off) red[t] += red[t + off];
        __syncthreads();
    }
    if (t == 0) d_gate[m] = 1.f / (1.f + expf(-(red[0] + gate_b[0])));
}

// =====================================================================
// K10: gen logits GEMM, mma.sync bf16 + ldmatrix + 3-stage cp.async.
// C[2048,32000] = comb_bf @ genW_bf^T + bias
// CTA tile 128x128, KC=64, warp tile 64x32 (8 warps).
// SMEM: SW128-swizzled 128B rows. grid=(M/128, N/128) m-fast.
// =====================================================================
__device__ __forceinline__ void mma_bf16(float& c0, float& c1, float& c2, float& c3,
                                         uint32_t a0, uint32_t a1, uint32_t a2, uint32_t a3,
                                         uint32_t b0, uint32_t b1)
{
    asm volatile(
        "mma.sync.aligned.m16n8k16.row.col.f32.bf16.bf16.f32 "
        "{%0,%1,%2,%3}, {%4,%5,%6,%7}, {%8,%9}, {%0,%1,%2,%3};\n"
        : "+f"(c0), "+f"(c1), "+f"(c2), "+f"(c3)
        : "r"(a0), "r"(a1), "r"(a2), "r"(a3), "r"(b0), "r"(b1));
}
__device__ __forceinline__ void cp16s(uint32_t saddr, const void* g)
{
    asm volatile("cp.async.cg.shared.global [%0], [%1], 16;\n" :: "r"(saddr), "l"(g));
}
__device__ __forceinline__ void ldsm4(uint32_t& r0, uint32_t& r1, uint32_t& r2,
                                      uint32_t& r3, uint32_t addr)
{
    asm volatile("ldmatrix.sync.aligned.m8n8.x4.shared.b16 {%0,%1,%2,%3}, [%4];"
                 : "=r"(r0), "=r"(r1), "=r"(r2), "=r"(r3) : "r"(addr));
}
#define SWZ(o) ((o) ^ (((o) >> 3) & 0x70))
#define GKC 64
#define GSTG 3
#define GSTAGE_BYTES 32768           // A 16KB + B 16KB
#define GSMEM (GSTG * GSTAGE_BYTES)  // 96KB

__global__ void __launch_bounds__(256, 2) k_gen_mma2(const float* __restrict__ bias)
{
    extern __shared__ __align__(1024) char gsm[];
    uint32_t sbase;
    asm("{ .reg .u64 t; cvta.to.shared.u64 t, %1; cvt.u32.u64 %0, t; }"
        : "=r"(sbase) : "l"(gsm));

    const int m0 = blockIdx.x * 128;
    const int n0 = blockIdx.y * 128;
    const int t = threadIdx.x;
    const int w = t >> 5, lane = t & 31;
    const int wm = (w >> 2) * 64;
    const int wn = (w & 3) * 32;
    const int g = lane >> 2, q = lane & 3;

    // ldmatrix per-lane offsets
    const int a_row = ((lane >> 3) & 1) * 8 + (lane & 7);
    const int a_colb = ((lane >> 4) & 1) * 16;            // bytes
    const int b_row = (lane >> 4) * 8 + (lane & 7);
    const int b_colb = ((lane >> 3) & 1) * 16;

    const char* Ag = (const char*)&d_comb_bf[(size_t)m0 * 1024];
    const char* Bg = (const char*)&d_genW_bf[(size_t)n0 * 1024];

    // loader mapping: 4 pieces of 16B per tile per thread
    const int lrow = t >> 1;                 // idx>>3 with it folding
    (void)lrow;

    float acc[4][4][4];
#pragma unroll
    for (int i = 0; i < 4; i++)
#pragma unroll
        for (int j = 0; j < 4; j++)
#pragma unroll
            for (int r = 0; r < 4; r++) acc[i][j][r] = 0.f;

    auto stage = [&](int st, int c) {
        uint32_t aB = sbase + st * GSTAGE_BYTES;
        uint32_t bB = aB + 16384;
        int kb = c * (GKC * 2);
#pragma unroll
        for (int it = 0; it < 4; it++) {
            int idx = it * 256 + t;
            int row = idx >> 3;
            int p = (idx & 7) * 16;
            cp16s(aB + SWZ(row * 128 + p), Ag + (size_t)row * 2048 + kb + p);
            cp16s(bB + SWZ(row * 128 + p), Bg + (size_t)row * 2048 + kb + p);
        }
        asm volatile("cp.async.commit_group;" ::);
    };

    stage(0, 0);
    stage(1, 1);

#pragma unroll 1
    for (int c = 0; c < 16; c++) {
        if (c < 15) asm volatile("cp.async.wait_group 1;" ::);
        else        asm volatile("cp.async.wait_group 0;" ::);
        __syncthreads();

        const int st = c % GSTG;
        const uint32_t aB = sbase + st * GSTAGE_BYTES;
        const uint32_t bB = aB + 16384;

#pragma unroll
        for (int kk = 0; kk < GKC; kk += 16) {
            uint32_t af[4][4];
#pragma unroll
            for (int i = 0; i < 4; i++) {
                int row = wm + i * 16 + a_row;
                ldsm4(af[i][0], af[i][1], af[i][2], af[i][3],
                      aB + SWZ(row * 128 + kk * 2 + a_colb));
            }
            uint32_t bf[4][2];
#pragma unroll
            for (int j2 = 0; j2 < 2; j2++) {
                int row = wn + j2 * 16 + b_row;
                ldsm4(bf[j2 * 2][0], bf[j2 * 2][1], bf[j2 * 2 + 1][0], bf[j2 * 2 + 1][1],
                      bB + SWZ(row * 128 + kk * 2 + b_colb));
            }
#pragma unroll
            for (int i = 0; i < 4; i++)
#pragma unroll
                for (int j = 0; j < 4; j++)
                    mma_bf16(acc[i][j][0], acc[i][j][1], acc[i][j][2], acc[i][j][3],
                             af[i][0], af[i][1], af[i][2], af[i][3],
                             bf[j][0], bf[j][1]);
        }
        __syncthreads();
        if (c + 2 < 16) stage((c + 2) % GSTG, c + 2);
    }

    // epilogue
#pragma unroll
    for (int j = 0; j < 4; j++) {
        int n = n0 + wn + j * 8 + q * 2;
        float2 bv = *(const float2*)&bias[n];
#pragma unroll
        for (int i = 0; i < 4; i++) {
            size_t r0 = (size_t)(m0 + wm + i * 16 + g);
            size_t r1 = r0 + 8;
            float2 o0 = {acc[i][j][0] + bv.x, acc[i][j][1] + bv.y};
            float2 o1 = {acc[i][j][2] + bv.x, acc[i][j][3] + bv.y};
            *(float2*)&d_logits[r0 * VV + n] = o0;
            *(float2*)&d_logits[r1 * VV + n] = o1;
        }
    }
}

// =====================================================================
// K11: fused row softmax over V + gate blend -> out
// =====================================================================
__global__ void k_softmaxV(float* __restrict__ out)
{
    int m = blockIdx.x;
    const float* row = d_logits + (size_t)m * VV;
    const int t = threadIdx.x;
    float mx = -1e30f, sm = 0.f;
    for (int v4 = t; v4 < VV / 4; v4 += 256) {
        float4 l = *(const float4*)&row[v4 * 4];
        float vals[4] = {l.x, l.y, l.z, l.w};
#pragma unroll
        for (int u = 0; u < 4; u++) {
            float l1 = vals[u];
            if (l1 > mx) { sm = sm * __expf(mx - l1) + 1.f; mx = l1; }
            else sm += __expf(l1 - mx);
        }
    }
    __shared__ float smx[256], ssm[256];
    smx[t] = mx; ssm[t] = sm;
    for (int off = 128; off > 0; off >>= 1) {
        __syncthreads();
        if (t < off) {
            float m2 = smx[t + off], s2 = ssm[t + off];
            if (m2 > mx) { sm = sm * __expf(mx - m2) + s2; mx = m2; }
            else sm += s2 * __expf(m2 - mx);
            smx[t] = mx; ssm[t] = sm;
        }
    }
    __syncthreads();
    mx = smx[0];
    float g = d_gate[m];
    float is = g / ssm[0];
    float* orow = out + (size_t)m * VV;
    for (int v4 = t; v4 < VV / 4; v4 += 256) {
        float4 l = *(const float4*)&row[v4 * 4];
        float4 o;
        o.x = __expf(l.x - mx) * is;
        o.y = __expf(l.y - mx) * is;
        o.z = __expf(l.z - mx) * is;
        o.w = __expf(l.w - mx) * is;
        *(float4*)&orow[v4 * 4] = o;
    }
}

// =====================================================================
// K13: scatter copy-probs
// =====================================================================
__global__ void k_scatter(const int* __restrict__ x, float* __restrict__ out)
{
    int m = blockIdx.x;
    int b = m >> 10;
    int i = m & (SS - 1);
    float om = 1.f - d_gate[m];
    const float* pr = d_probs + (size_t)m * SS;
    float* orow = out + (size_t)m * VV;
    for (int j = threadIdx.x; j <= i; j += 256) {
        atomicAdd(&orow[x[b * SS + j]], om * pr[j]);
    }
}

// =====================================================================
// launch
// =====================================================================
extern "C" void kernel_launch(void* const* d_in, const int* in_sizes, int n_in,
                              void* d_out, int out_size)
{
    const int*   x        = (const int*)d_in[0];
    const float* tok_emb  = (const float*)d_in[1];
    const float* pos_emb  = (const float*)d_in[2];
    const float* W_ih     = (const float*)d_in[3];
    const float* W_hh     = (const float*)d_in[4];
    const float* b_ih     = (const float*)d_in[5];
    const float* b_hh     = (const float*)d_in[6];
    const float* W_q      = (const float*)d_in[7];
    const float* W_k      = (const float*)d_in[8];
    const float* gen_W    = (const float*)d_in[9];
    const float* gen_b    = (const float*)d_in[10];
    const float* gate_W   = (const float*)d_in[11];
    const float* gate_b   = (const float*)d_in[12];
    float* out = (float*)d_out;

    cudaFuncSetAttribute(k_gen_mma2, cudaFuncAttributeMaxDynamicSharedMemorySize,
                         GSMEM);

    k_xproj<<<dim3(G3 / 64, MM / 64), 256>>>(x, tok_emb, pos_emb, W_ih, b_ih);
    k_init<<<1, 256>>>();
    k_convW<<<(VV * 2 * DD) / (8 * 256), 256>>>(gen_W);
    k_gru<<<GRU_CTAS, 256>>>(W_hh, b_hh);
    k_qk<0><<<dim3(DD / 64, MM / 64), 256>>>(W_q);
    k_qk<1><<<dim3(DD / 64, MM / 64), 256>>>(W_k);
    k_rope<<<MM, 256>>>();
    k_scores<<<dim3(SS / 64, SS / 64, BB), 256>>>();
    k_softmax_rows<<<MM, 256>>>();
    k_ctx<<<dim3(DD / 64, SS / 64, BB), 256>>>();
    k_comb_gate<<<MM, 256>>>(gate_W, gate_b);
    k_gen_mma2<<<dim3(MM / 128, VV / 128), 256, GSMEM>>>(gen_b);
    k_softmaxV<<<MM, 256>>>(out);
    k_scatter<<<MM, 256>>>(x, out);
}